// round 11
// baseline (speedup 1.0000x reference)
#include <cuda_runtime.h>
#include <cuda_bf16.h>
#include <math_constants.h>

// Problem constants
#define BB   2
#define LL   2048
#define CC   512
#define HH   8
#define DD   64
#define MM   (BB*LL)          // 4096 rows
#define NQKV (3*CC)           // 1536
#define NQ   16               // L/128 (mask Q-block granularity)
#define NK   32               // L/64
#define SCALE 0.125f          // D^-0.5
#define SIMTH 0.6f
#define CDFTH 0.98f

// Scratch (allocation-free rule -> device globals)
__device__ float g_q[BB*HH*LL*DD];        // raw [B,H,L,D] (meansim)
__device__ float g_k[BB*HH*LL*DD];        // raw [B,H,L,D] (meansim)
__device__ float g_qp[BB*HH*NQ*8192];     // Q A-fragments, tf32(q*SCALE)  (128x64)
__device__ float g_kp[BB*HH*NK*4096];     // K B-frag pairs, tf32          (64x64)
__device__ float g_vp[BB*HH*NK*4096];     // V B-frag pairs, tf32          (64x64)
__device__ float g_o[BB*LL*CC];           // [B,L,C]
__device__ int   g_mask[BB*HH*NQ*NK];     // 1 = keep block
__device__ float g_qm[BB*HH][NQ][DD];
__device__ float g_km[BB*HH][NK][DD];
__device__ float g_qsim[BB*HH][NQ];
__device__ float g_ksim[BB*HH][NK];

__device__ __forceinline__ unsigned f2tf32(float x) {
    unsigned r;
    asm("cvt.rna.tf32.f32 %0, %1;" : "=r"(r) : "f"(x));
    return r;
}
__device__ __forceinline__ float tf32f(float x) {
    return __uint_as_float(f2tf32(x));
}

__device__ __forceinline__ void mma_tf32(float c[4],
                                         unsigned a0, unsigned a1, unsigned a2, unsigned a3,
                                         unsigned b0, unsigned b1) {
    asm volatile(
        "mma.sync.aligned.m16n8k8.row.col.f32.tf32.tf32.f32 "
        "{%0,%1,%2,%3}, {%4,%5,%6,%7}, {%8,%9}, {%0,%1,%2,%3};"
        : "+f"(c[0]), "+f"(c[1]), "+f"(c[2]), "+f"(c[3])
        : "r"(a0), "r"(a1), "r"(a2), "r"(a3), "r"(b0), "r"(b1));
}

__device__ __forceinline__ void cp16(unsigned smem_dst, const void* gsrc) {
    asm volatile("cp.async.ca.shared.global [%0], [%1], 16;"
                 :: "r"(smem_dst), "l"(gsrc));
}

__device__ __forceinline__ void atomicMinFloat(float* addr, float val) {
    int* ia = (int*)addr;
    int old = *ia;
    while (__int_as_float(old) > val) {
        int assumed = old;
        old = atomicCAS(ia, assumed, __float_as_int(val));
        if (old == assumed) break;
    }
}

// ---------------------------------------------------------------------------
// tf32 tensor-core GEMM: C[M,N] = A[M,K=512] @ B[K,N] + bias
// 128x64 tile, 256 threads = 8 warps (4M x 2N), cp.async double-buffered.
// SCATTER=true: writes raw q/k + fragment-packed qp/kp/vp.
// ---------------------------------------------------------------------------
#define GA_ST 36
#define GB_ST 72
#define GA_FL (128*GA_ST)          // 4608
#define GB_FL (32*GB_ST)           // 2304
#define GEMM_SMEM_FLOATS (2*GA_FL + 2*GB_FL)
#define GEMM_SMEM_BYTES  (GEMM_SMEM_FLOATS*4)

extern __shared__ float sm_dyn[];

template<int N, bool SCATTER>
__global__ void __launch_bounds__(256) gemm_tf32(const float* __restrict__ A,
                                                 const float* __restrict__ Bw,
                                                 const float* __restrict__ bias,
                                                 float* __restrict__ out) {
    const int K = CC;
    const float* Ap = SCATTER ? A : (const float*)g_o;
    int m0 = blockIdx.y * 128, n0 = blockIdx.x * 64;
    float* Asm = sm_dyn;
    float* Bsm = sm_dyn + 2 * GA_FL;
    unsigned sbase = (unsigned)__cvta_generic_to_shared(sm_dyn);
    int tid = threadIdx.x;
    int wid = tid >> 5, lane = tid & 31;
    int lr = lane >> 2, lc = lane & 3;
    int warp_m = wid & 3, warp_n = wid >> 2;

    float c[2][4][4] = {};

    auto stage = [&](int buf, int k0) {
        unsigned a_s = sbase + (unsigned)(buf * GA_FL) * 4u;
        unsigned b_s = sbase + (unsigned)(2 * GA_FL + buf * GB_FL) * 4u;
        #pragma unroll
        for (int i = 0; i < 4; i++) {
            int f4 = tid + i * 256;
            int r = f4 >> 3, cg = f4 & 7;
            cp16(a_s + (unsigned)(r * GA_ST + cg * 4) * 4u,
                 &Ap[(size_t)(m0 + r) * K + k0 + cg * 4]);
        }
        #pragma unroll
        for (int i = 0; i < 2; i++) {
            int f4 = tid + i * 256;
            int r = f4 >> 4, ng = f4 & 15;
            cp16(b_s + (unsigned)(r * GB_ST + ng * 4) * 4u,
                 &Bw[(size_t)(k0 + r) * N + n0 + ng * 4]);
        }
        asm volatile("cp.async.commit_group;");
    };

    stage(0, 0);
    const int NCHUNK = K / 32;
    for (int ch = 0; ch < NCHUNK; ch++) {
        int buf = ch & 1;
        if (ch < NCHUNK - 1) {
            stage(buf ^ 1, (ch + 1) * 32);
            asm volatile("cp.async.wait_group 1;");
        } else {
            asm volatile("cp.async.wait_group 0;");
        }
        __syncthreads();

        const float* Aw = Asm + buf * GA_FL + (warp_m * 32) * GA_ST;
        const float* Bb = Bsm + buf * GB_FL;
        #pragma unroll
        for (int kk = 0; kk < 4; kk++) {
            int kf = kk * 8;
            unsigned a[2][4];
            #pragma unroll
            for (int mt = 0; mt < 2; mt++) {
                a[mt][0] = f2tf32(Aw[(mt * 16 + lr    ) * GA_ST + kf + lc    ]);
                a[mt][1] = f2tf32(Aw[(mt * 16 + lr + 8) * GA_ST + kf + lc    ]);
                a[mt][2] = f2tf32(Aw[(mt * 16 + lr    ) * GA_ST + kf + lc + 4]);
                a[mt][3] = f2tf32(Aw[(mt * 16 + lr + 8) * GA_ST + kf + lc + 4]);
            }
            unsigned bf[4][2];
            #pragma unroll
            for (int nt = 0; nt < 4; nt++) {
                int nn = warp_n * 32 + nt * 8 + lr;
                bf[nt][0] = f2tf32(Bb[(kf + lc    ) * GB_ST + nn]);
                bf[nt][1] = f2tf32(Bb[(kf + lc + 4) * GB_ST + nn]);
            }
            #pragma unroll
            for (int mt = 0; mt < 2; mt++)
                #pragma unroll
                for (int nt = 0; nt < 4; nt++)
                    mma_tf32(c[mt][nt], a[mt][0], a[mt][1], a[mt][2], a[mt][3],
                             bf[nt][0], bf[nt][1]);
        }
        __syncthreads();
    }

    // Epilogue
    int t = n0 >> 9;   // uniform per CTA when SCATTER
    #pragma unroll
    for (int mt = 0; mt < 2; mt++) {
        #pragma unroll
        for (int half = 0; half < 2; half++) {
            int row = m0 + warp_m * 32 + mt * 16 + lr + half * 8;
            #pragma unroll
            for (int nt = 0; nt < 4; nt++) {
                int col = n0 + warp_n * 32 + nt * 8 + 2 * lc;
                float v0 = c[mt][nt][half * 2 + 0] + bias[col];
                float v1 = c[mt][nt][half * 2 + 1] + bias[col + 1];
                if (SCATTER) {
                    int b = row >> 11, l = row & 2047;
                    int h = (col & 511) >> 6;
                    int d = col & 63, d1 = d + 1;
                    int bh = b * HH + h;
                    if (t == 0) {
                        *(float2*)&g_q[((size_t)bh * LL + l) * DD + d] =
                            make_float2(v0, v1);
                        int qt = l >> 7, r = l & 127;
                        int w = r >> 4, lr2 = r & 7, hf = (r >> 3) & 1;
                        float* qp = g_qp + ((size_t)(bh * NQ + qt)) * 8192 + w * 1024;
                        qp[(d  >> 3) * 128 + (lr2 * 4 + (d  & 3)) * 4 + hf + 2 * ((d  >> 2) & 1)]
                            = tf32f(v0 * SCALE);
                        qp[(d1 >> 3) * 128 + (lr2 * 4 + (d1 & 3)) * 4 + hf + 2 * ((d1 >> 2) & 1)]
                            = tf32f(v1 * SCALE);
                    } else if (t == 1) {
                        *(float2*)&g_k[((size_t)bh * LL + l) * DD + d] =
                            make_float2(v0, v1);
                        int kb = l >> 6, n = l & 63;
                        float* kp = g_kp + ((size_t)(bh * NK + kb)) * 4096 + n * 8;
                        kp[(d  >> 3) * 512 + (d  & 3) * 2 + ((d  >> 2) & 1)] = tf32f(v0);
                        kp[(d1 >> 3) * 512 + (d1 & 3) * 2 + ((d1 >> 2) & 1)] = tf32f(v1);
                    } else {
                        int kb = l >> 6, k64 = l & 63;
                        float* vp = g_vp + ((size_t)(bh * NK + kb)) * 4096
                                  + (k64 >> 3) * 512 + (k64 & 3) * 2 + ((k64 >> 2) & 1);
                        vp[d  * 8] = tf32f(v0);
                        vp[d1 * 8] = tf32f(v1);
                    }
                } else {
                    *(float2*)&out[(size_t)row * N + col] = make_float2(v0, v1);
                }
            }
        }
    }
}

// ---------------------------------------------------------------------------
// Kernel 2a: per-block mean + min-cosine.
// ---------------------------------------------------------------------------
__global__ void __launch_bounds__(256) meansim_kernel() {
    int bh = blockIdx.y;
    int j  = blockIdx.x;
    bool isQ = j < NQ;
    int blk  = isQ ? j : j - NQ;
    int rows = isQ ? 128 : 64;
    const float* base = (isQ ? g_q : g_k) + (size_t)bh * LL * DD + (size_t)blk * rows * DD;
    __shared__ float psum[256];
    __shared__ float mean[64];
    __shared__ float nrm;
    __shared__ float simv;
    int tid = threadIdx.x;
    if (tid == 0) simv = 1e30f;

    {
        int d = tid & 63, rg = tid >> 6;
        float acc = 0.f;
        for (int r = rg; r < rows; r += 4) acc += base[r * DD + d];
        psum[tid] = acc;
    }
    __syncthreads();
    if (tid < 64) {
        float m = (psum[tid] + psum[tid + 64] + psum[tid + 128] + psum[tid + 192])
                  * (1.f / rows);
        mean[tid] = m;
        float* gm = isQ ? &g_qm[bh][blk][0] : &g_km[bh][blk][0];
        gm[tid] = m;
    }
    __syncthreads();
    if (tid < 32) {
        float s = mean[tid] * mean[tid] + mean[tid + 32] * mean[tid + 32];
        #pragma unroll
        for (int o = 16; o >= 1; o >>= 1) s += __shfl_xor_sync(0xffffffffu, s, o);
        if (tid == 0) nrm = sqrtf(s);
    }
    __syncthreads();
    float mnorm = nrm;

    float cosv;
    if (isQ) {
        int row = tid >> 1, half = tid & 1;
        const float* p  = base + row * DD + half * 32;
        const float* mp = mean + half * 32;
        float dot = 0.f, nn = 0.f;
        #pragma unroll
        for (int d = 0; d < 32; d++) { float v = p[d]; dot += v * mp[d]; nn += v * v; }
        dot += __shfl_xor_sync(0xffffffffu, dot, 1);
        nn  += __shfl_xor_sync(0xffffffffu, nn,  1);
        cosv = dot / ((sqrtf(nn) + 1e-6f) * (mnorm + 1e-6f));
    } else {
        int row = tid >> 2, qd = tid & 3;
        const float* p  = base + row * DD + qd * 16;
        const float* mp = mean + qd * 16;
        float dot = 0.f, nn = 0.f;
        #pragma unroll
        for (int d = 0; d < 16; d++) { float v = p[d]; dot += v * mp[d]; nn += v * v; }
        dot += __shfl_xor_sync(0xffffffffu, dot, 1);
        dot += __shfl_xor_sync(0xffffffffu, dot, 2);
        nn  += __shfl_xor_sync(0xffffffffu, nn,  1);
        nn  += __shfl_xor_sync(0xffffffffu, nn,  2);
        cosv = dot / ((sqrtf(nn) + 1e-6f) * (mnorm + 1e-6f));
    }
    #pragma unroll
    for (int o = 16; o >= 1; o >>= 1)
        cosv = fminf(cosv, __shfl_xor_sync(0xffffffffu, cosv, o));
    if ((tid & 31) == 0) atomicMinFloat(&simv, cosv);
    __syncthreads();
    if (tid == 0) {
        if (isQ) g_qsim[bh][blk] = simv; else g_ksim[bh][blk] = simv;
    }
}

// ---------------------------------------------------------------------------
// Kernel 2b: pooled softmax + CDF keep -> block mask.
// ---------------------------------------------------------------------------
__global__ void __launch_bounds__(256) mask_kernel() {
    int bh = blockIdx.x;
    __shared__ float pooled[NQ][NK];
    __shared__ float qs[NQ], kss[NK];
    int tid = threadIdx.x;
    if (tid < NQ) qs[tid]  = g_qsim[bh][tid];
    if (tid < NK) kss[tid] = g_ksim[bh][tid];
    for (int e = tid; e < NQ * NK; e += 256) {
        int qi = e >> 5, ki = e & 31;
        const float* a = g_qm[bh][qi];
        const float* b = g_km[bh][ki];
        float dot = 0.f;
        #pragma unroll
        for (int d = 0; d < DD; d++) dot += a[d] * b[d];
        pooled[qi][ki] = dot * SCALE;
    }
    __syncthreads();
    if (tid < NQ) {
        float vals[NK]; int idx[NK];
        float mx = -CUDART_INF_F;
        for (int i = 0; i < NK; i++) mx = fmaxf(mx, pooled[tid][i]);
        float sum = 0.f;
        for (int i = 0; i < NK; i++) { vals[i] = expf(pooled[tid][i] - mx); sum += vals[i]; }
        float inv = 1.f / sum;
        for (int i = 0; i < NK; i++) { vals[i] *= inv; idx[i] = i; }
        for (int i = 1; i < NK; i++) {
            float kv = vals[i]; int ki = idx[i];
            int j = i - 1;
            while (j >= 0 && vals[j] < kv) { vals[j+1] = vals[j]; idx[j+1] = idx[j]; j--; }
            vals[j+1] = kv; idx[j+1] = ki;
        }
        unsigned keep = 0u;
        float csum = 0.f;
        for (int i = 0; i < NK; i++) {
            if (csum < CDFTH) keep |= (1u << idx[i]);
            csum += vals[i];
        }
        bool qself = qs[tid] > SIMTH;
        int* mrow = g_mask + (bh * NQ + tid) * NK;
        for (int ki = 0; ki < NK; ki++) {
            bool kself = kss[ki] > SIMTH;
            mrow[ki] = (((keep >> ki) & 1u) || !qself || !kself) ? 1 : 0;
        }
    }
}

// ---------------------------------------------------------------------------
// Kernel 3: block-sparse flash attention, tf32 mma, fragment-packed operands,
// K/V double-buffered cp.async prefetch + fused per-slice PV.
// grid = (16 q-tiles of 128 rows, 16 bh), 256 threads = 8 warps.
// smem: Qp[8192] | K0[4096] K1[4096] | V0[4096] V1[4096] | Pslice[8w][2][128]
//     = 26624 floats = 104 KB  -> 2 CTAs/SM.
// ---------------------------------------------------------------------------
#define ATT_QP_FL 8192
#define ATT_KV_FL 4096
#define ATT_SMEM_FLOATS (ATT_QP_FL + 4*ATT_KV_FL + 8*256)   // 26624
#define ATT_SMEM_BYTES  (ATT_SMEM_FLOATS * 4)               // 106496

__global__ void __launch_bounds__(256, 2) attn_tf32() {
    const int qb = blockIdx.x;
    const int bh = blockIdx.y;
    const int b = bh >> 3, h = bh & 7;
    const int tid  = threadIdx.x;
    const int wid  = tid >> 5;
    const int lane = tid & 31;
    const int lr = lane >> 2;
    const int lc = lane & 3;

    float* Qp   = sm_dyn;                                   // [8 w][8 kk][32 lane][4]
    float* Kbuf = sm_dyn + ATT_QP_FL;                       // [2][4096]
    float* Vbuf = Kbuf + 2 * ATT_KV_FL;                     // [2][4096]
    float* Psl  = Vbuf + 2 * ATT_KV_FL + wid * 256;         // [2][128] per warp
    unsigned sbase = (unsigned)__cvta_generic_to_shared(sm_dyn);
    unsigned kbuf_u = sbase + (unsigned)ATT_QP_FL * 4u;
    unsigned vbuf_u = kbuf_u + 2u * ATT_KV_FL * 4u;

    __shared__ int s_list[NK];
    __shared__ int s_nk;

    // Stage Q fragments (precomputed, tf32*scale): 8192 floats
    const float* qsrc = g_qp + ((size_t)(bh * NQ + qb)) * 8192;
    #pragma unroll
    for (int i = 0; i < 8; i++)
        cp16(sbase + (unsigned)(tid + i * 256) * 16u, qsrc + (tid + i * 256) * 4);
    asm volatile("cp.async.commit_group;");

    // Kept-block list
    const int* mrow = g_mask + (bh * NQ + qb) * NK;
    if (tid == 0) {
        int c = 0;
        for (int i = 0; i < NK; i++) if (mrow[i]) s_list[c++] = i;
        s_nk = c;
    }
    __syncthreads();
    const int nkeep = s_nk;

    const float* kgp = g_kp + (size_t)bh * NK * 4096;
    const float* vgp = g_vp + (size_t)bh * NK * 4096;

    auto stage_kv = [&](int buf, int kb) {
        const float* ks = kgp + (size_t)kb * 4096;
        const float* vs = vgp + (size_t)kb * 4096;
        unsigned ko = kbuf_u + (unsigned)(buf * ATT_KV_FL) * 4u;
        unsigned vo = vbuf_u + (unsigned)(buf * ATT_KV_FL) * 4u;
        #pragma unroll
        for (int i = 0; i < 4; i++) {
            unsigned off = (unsigned)(tid + i * 256) * 16u;
            cp16(ko + off, ks + (tid + i * 256) * 4);
            cp16(vo + off, vs + (tid + i * 256) * 4);
        }
        asm volatile("cp.async.commit_group;");
    };

    stage_kv(0, s_list[0]);

    float o[8][4];
    #pragma unroll
    for (int nt = 0; nt < 8; nt++)
        #pragma unroll
        for (int j = 0; j < 4; j++) o[nt][j] = 0.f;
    float m0r = -CUDART_INF_F, m1r = -CUDART_INF_F;
    float l0 = 0.f, l1 = 0.f;

    const float* QpW = Qp + wid * 1024;

    for (int i = 0; i < nkeep; i++) {
        int buf = i & 1;
        asm volatile("cp.async.wait_group 0;");
        __syncthreads();               // data visible + prev reads of other buf done
        if (i + 1 < nkeep) stage_kv(buf ^ 1, s_list[i + 1]);

        const float* Kp = Kbuf + buf * ATT_KV_FL;
        const float* Vp = Vbuf + buf * ATT_KV_FL;

        // S = Q K^T
        float sc[8][4];
        #pragma unroll
        for (int nt = 0; nt < 8; nt++)
            #pragma unroll
            for (int j = 0; j < 4; j++) sc[nt][j] = 0.f;

        #pragma unroll
        for (int kk = 0; kk < 8; kk++) {
            float4 av = *(const float4*)(QpW + kk * 128 + lane * 4);
            unsigned a0 = __float_as_uint(av.x), a1 = __float_as_uint(av.y);
            unsigned a2 = __float_as_uint(av.z), a3 = __float_as_uint(av.w);
            const float* kbase = Kp + kk * 512 + lr * 8 + lc * 2;
            #pragma unroll
            for (int nt = 0; nt < 8; nt++) {
                float2 bv = *(const float2*)(kbase + nt * 64);
                mma_tf32(sc[nt], a0, a1, a2, a3,
                         __float_as_uint(bv.x), __float_as_uint(bv.y));
            }
        }

        // Online softmax maxes (rows lr, lr+8)
        float rl = -CUDART_INF_F, rh = -CUDART_INF_F;
        #pragma unroll
        for (int nt = 0; nt < 8; nt++) {
            rl = fmaxf(rl, fmaxf(sc[nt][0], sc[nt][1]));
            rh = fmaxf(rh, fmaxf(sc[nt][2], sc[nt][3]));
        }
        rl = fmaxf(rl, __shfl_xor_sync(0xffffffffu, rl, 1));
        rl = fmaxf(rl, __shfl_xor_sync(0xffffffffu, rl, 2));
        rh = fmaxf(rh, __shfl_xor_sync(0xffffffffu, rh, 1));
        rh = fmaxf(rh, __shfl_xor_sync(0xffffffffu, rh, 2));
        float mn0 = fmaxf(m0r, rl), mn1 = fmaxf(m1r, rh);
        float c0 = __expf(m0r - mn0), c1 = __expf(m1r - mn1);
        #pragma unroll
        for (int nt = 0; nt < 8; nt++) {
            o[nt][0] *= c0; o[nt][1] *= c0;
            o[nt][2] *= c1; o[nt][3] *= c1;
        }

        // Fused: per kpos-slice nt, exp -> P slice -> O += P_nt @ V_nt
        float s0 = 0.f, s1 = 0.f;
        #pragma unroll
        for (int nt = 0; nt < 8; nt++) {
            float p0 = __expf(sc[nt][0] - mn0);
            float p1 = __expf(sc[nt][1] - mn0);
            float p2 = __expf(sc[nt][2] - mn1);
            float p3 = __expf(sc[nt][3] - mn1);
            s0 += p0 + p1; s1 += p2 + p3;
            float* Pb = Psl + (nt & 1) * 128;
            // layout [2 c2][32 lane][2]: c2=0 holds (p0,p2), c2=1 holds (p1,p3)
            *(float2*)(Pb +      lane * 2) = make_float2(tf32f(p0), tf32f(p2));
            *(float2*)(Pb + 64 + lane * 2) = make_float2(tf32f(p1), tf32f(p3));
            __syncwarp();
            const float* pb = Pb + (lc & 1) * 64 + (lr * 4 + (lc >> 1)) * 2;
            float2 A01 = *(const float2*)pb;        // P[lr][8nt+lc], P[lr+8][..]
            float2 A23 = *(const float2*)(pb + 4);  // cols +4
            unsigned a0 = __float_as_uint(A01.x), a1 = __float_as_uint(A01.y);
            unsigned a2 = __float_as_uint(A23.x), a3 = __float_as_uint(A23.y);
            const float* vbase = Vp + nt * 512 + lr * 8 + lc * 2;
            #pragma unroll
            for (int nt2 = 0; nt2 < 8; nt2++) {
                float2 bv = *(const float2*)(vbase + nt2 * 64);
                mma_tf32(o[nt2], a0, a1, a2, a3,
                         __float_as_uint(bv.x), __float_as_uint(bv.y));
            }
        }
        s0 += __shfl_xor_sync(0xffffffffu, s0, 1);
        s0 += __shfl_xor_sync(0xffffffffu, s0, 2);
        s1 += __shfl_xor_sync(0xffffffffu, s1, 1);
        s1 += __shfl_xor_sync(0xffffffffu, s1, 2);
        l0 = l0 * c0 + s0;
        l1 = l1 * c1 + s1;
        m0r = mn0; m1r = mn1;
    }

    // Epilogue: normalize and scatter to g_o
    float inv0 = 1.f / l0, inv1 = 1.f / l1;
    int r0 = qb * 128 + wid * 16 + lr;
    float* og = g_o + (size_t)b * LL * CC + h * DD;
    #pragma unroll
    for (int nt = 0; nt < 8; nt++) {
        float2 w0 = make_float2(o[nt][0] * inv0, o[nt][1] * inv0);
        float2 w1 = make_float2(o[nt][2] * inv1, o[nt][3] * inv1);
        *(float2*)&og[(size_t)(r0    ) * CC + nt * 8 + 2 * lc] = w0;
        *(float2*)&og[(size_t)(r0 + 8) * CC + nt * 8 + 2 * lc] = w1;
    }
}

// ---------------------------------------------------------------------------
extern "C" void kernel_launch(void* const* d_in, const int* in_sizes, int n_in,
                              void* d_out, int out_size) {
    const float* x     = (const float*)d_in[0];
    const float* Wqkv  = (const float*)d_in[1];
    const float* bqkv  = (const float*)d_in[2];
    const float* Wproj = (const float*)d_in[3];
    const float* bproj = (const float*)d_in[4];
    float* out = (float*)d_out;

    cudaFuncSetAttribute(attn_tf32, cudaFuncAttributeMaxDynamicSharedMemorySize,
                         ATT_SMEM_BYTES);
    cudaFuncSetAttribute(gemm_tf32<NQKV, true>,
                         cudaFuncAttributeMaxDynamicSharedMemorySize, GEMM_SMEM_BYTES);
    cudaFuncSetAttribute(gemm_tf32<CC, false>,
                         cudaFuncAttributeMaxDynamicSharedMemorySize, GEMM_SMEM_BYTES);

    gemm_tf32<NQKV, true><<<dim3(NQKV / 64, MM / 128), 256, GEMM_SMEM_BYTES>>>(
        x, Wqkv, bqkv, nullptr);
    meansim_kernel<<<dim3(NQ + NK, BB * HH), 256>>>();
    mask_kernel<<<BB * HH, 256>>>();
    attn_tf32<<<dim3(NQ, BB * HH), 256, ATT_SMEM_BYTES>>>();
    gemm_tf32<CC, false><<<dim3(CC / 64, MM / 128), 256, GEMM_SMEM_BYTES>>>(
        nullptr, Wproj, bproj, out);
}

// round 12
// speedup vs baseline: 1.5421x; 1.5421x over previous
#include <cuda_runtime.h>
#include <cuda_bf16.h>
#include <math_constants.h>

// Problem constants
#define BB   2
#define LL   2048
#define CC   512
#define HH   8
#define DD   64
#define MM   (BB*LL)          // 4096 rows
#define NQKV (3*CC)           // 1536
#define NQ   16               // L/128 (mask Q-block granularity)
#define NK   32               // L/64
#define SCALE 0.125f          // D^-0.5
#define SIMTH 0.6f
#define CDFTH 0.98f

// Scratch (allocation-free rule -> device globals)
__device__ float g_q[BB*HH*LL*DD];        // raw [B,H,L,D] (meansim)
__device__ float g_k[BB*HH*LL*DD];        // raw [B,H,L,D] (meansim)
__device__ float g_qp[BB*HH*NQ*8192];     // Q A-fragments, tf32(q*SCALE)  (128x64)
__device__ float g_kp[BB*HH*NK*4096];     // K B-frag pairs, tf32          (64x64)
__device__ float g_vp[BB*HH*NK*4096];     // V B-frag pairs, tf32          (64x64)
__device__ float g_o[BB*LL*CC];           // [B,L,C]
__device__ int   g_mask[BB*HH*NQ*NK];     // 1 = keep block
__device__ float g_qm[BB*HH][NQ][DD];
__device__ float g_km[BB*HH][NK][DD];
__device__ float g_qsim[BB*HH][NQ];
__device__ float g_ksim[BB*HH][NK];

__device__ __forceinline__ unsigned f2tf32(float x) {
    unsigned r;
    asm("cvt.rna.tf32.f32 %0, %1;" : "=r"(r) : "f"(x));
    return r;
}
__device__ __forceinline__ float tf32f(float x) {
    return __uint_as_float(f2tf32(x));
}

__device__ __forceinline__ void mma_tf32(float c[4],
                                         unsigned a0, unsigned a1, unsigned a2, unsigned a3,
                                         unsigned b0, unsigned b1) {
    asm volatile(
        "mma.sync.aligned.m16n8k8.row.col.f32.tf32.tf32.f32 "
        "{%0,%1,%2,%3}, {%4,%5,%6,%7}, {%8,%9}, {%0,%1,%2,%3};"
        : "+f"(c[0]), "+f"(c[1]), "+f"(c[2]), "+f"(c[3])
        : "r"(a0), "r"(a1), "r"(a2), "r"(a3), "r"(b0), "r"(b1));
}

__device__ __forceinline__ void cp16(unsigned smem_dst, const void* gsrc) {
    asm volatile("cp.async.ca.shared.global [%0], [%1], 16;"
                 :: "r"(smem_dst), "l"(gsrc));
}

__device__ __forceinline__ void atomicMinFloat(float* addr, float val) {
    int* ia = (int*)addr;
    int old = *ia;
    while (__int_as_float(old) > val) {
        int assumed = old;
        old = atomicCAS(ia, assumed, __float_as_int(val));
        if (old == assumed) break;
    }
}

// ---------------------------------------------------------------------------
// tf32 tensor-core GEMM: C[M,N] = A[M,K=512] @ B[K,N] + bias
// 128x64 tile, 256 threads = 8 warps (4M x 2N), cp.async double-buffered.
// SCATTER=true: writes raw q/k + fragment-packed qp/kp/vp.
// ---------------------------------------------------------------------------
#define GA_ST 36
#define GB_ST 72
#define GA_FL (128*GA_ST)          // 4608
#define GB_FL (32*GB_ST)           // 2304
#define GEMM_SMEM_FLOATS (2*GA_FL + 2*GB_FL)
#define GEMM_SMEM_BYTES  (GEMM_SMEM_FLOATS*4)

extern __shared__ float sm_dyn[];

template<int N, bool SCATTER>
__global__ void __launch_bounds__(256) gemm_tf32(const float* __restrict__ A,
                                                 const float* __restrict__ Bw,
                                                 const float* __restrict__ bias,
                                                 float* __restrict__ out) {
    const int K = CC;
    const float* Ap = SCATTER ? A : (const float*)g_o;
    int m0 = blockIdx.y * 128, n0 = blockIdx.x * 64;
    float* Asm = sm_dyn;
    float* Bsm = sm_dyn + 2 * GA_FL;
    unsigned sbase = (unsigned)__cvta_generic_to_shared(sm_dyn);
    int tid = threadIdx.x;
    int wid = tid >> 5, lane = tid & 31;
    int lr = lane >> 2, lc = lane & 3;
    int warp_m = wid & 3, warp_n = wid >> 2;

    float c[2][4][4] = {};

    auto stage = [&](int buf, int k0) {
        unsigned a_s = sbase + (unsigned)(buf * GA_FL) * 4u;
        unsigned b_s = sbase + (unsigned)(2 * GA_FL + buf * GB_FL) * 4u;
        #pragma unroll
        for (int i = 0; i < 4; i++) {
            int f4 = tid + i * 256;
            int r = f4 >> 3, cg = f4 & 7;
            cp16(a_s + (unsigned)(r * GA_ST + cg * 4) * 4u,
                 &Ap[(size_t)(m0 + r) * K + k0 + cg * 4]);
        }
        #pragma unroll
        for (int i = 0; i < 2; i++) {
            int f4 = tid + i * 256;
            int r = f4 >> 4, ng = f4 & 15;
            cp16(b_s + (unsigned)(r * GB_ST + ng * 4) * 4u,
                 &Bw[(size_t)(k0 + r) * N + n0 + ng * 4]);
        }
        asm volatile("cp.async.commit_group;");
    };

    stage(0, 0);
    const int NCHUNK = K / 32;
    for (int ch = 0; ch < NCHUNK; ch++) {
        int buf = ch & 1;
        if (ch < NCHUNK - 1) {
            stage(buf ^ 1, (ch + 1) * 32);
            asm volatile("cp.async.wait_group 1;");
        } else {
            asm volatile("cp.async.wait_group 0;");
        }
        __syncthreads();

        const float* Aw = Asm + buf * GA_FL + (warp_m * 32) * GA_ST;
        const float* Bb = Bsm + buf * GB_FL;
        #pragma unroll
        for (int kk = 0; kk < 4; kk++) {
            int kf = kk * 8;
            unsigned a[2][4];
            #pragma unroll
            for (int mt = 0; mt < 2; mt++) {
                a[mt][0] = f2tf32(Aw[(mt * 16 + lr    ) * GA_ST + kf + lc    ]);
                a[mt][1] = f2tf32(Aw[(mt * 16 + lr + 8) * GA_ST + kf + lc    ]);
                a[mt][2] = f2tf32(Aw[(mt * 16 + lr    ) * GA_ST + kf + lc + 4]);
                a[mt][3] = f2tf32(Aw[(mt * 16 + lr + 8) * GA_ST + kf + lc + 4]);
            }
            unsigned bf[4][2];
            #pragma unroll
            for (int nt = 0; nt < 4; nt++) {
                int nn = warp_n * 32 + nt * 8 + lr;
                bf[nt][0] = f2tf32(Bb[(kf + lc    ) * GB_ST + nn]);
                bf[nt][1] = f2tf32(Bb[(kf + lc + 4) * GB_ST + nn]);
            }
            #pragma unroll
            for (int mt = 0; mt < 2; mt++)
                #pragma unroll
                for (int nt = 0; nt < 4; nt++)
                    mma_tf32(c[mt][nt], a[mt][0], a[mt][1], a[mt][2], a[mt][3],
                             bf[nt][0], bf[nt][1]);
        }
        __syncthreads();
    }

    // Epilogue
    int t = n0 >> 9;   // uniform per CTA when SCATTER
    #pragma unroll
    for (int mt = 0; mt < 2; mt++) {
        #pragma unroll
        for (int half = 0; half < 2; half++) {
            int row = m0 + warp_m * 32 + mt * 16 + lr + half * 8;
            #pragma unroll
            for (int nt = 0; nt < 4; nt++) {
                int col = n0 + warp_n * 32 + nt * 8 + 2 * lc;
                float v0 = c[mt][nt][half * 2 + 0] + bias[col];
                float v1 = c[mt][nt][half * 2 + 1] + bias[col + 1];
                if (SCATTER) {
                    int b = row >> 11, l = row & 2047;
                    int h = (col & 511) >> 6;
                    int d = col & 63, d1 = d + 1;
                    int bh = b * HH + h;
                    if (t == 0) {
                        *(float2*)&g_q[((size_t)bh * LL + l) * DD + d] =
                            make_float2(v0, v1);
                        int qt = l >> 7, r = l & 127;
                        int w = r >> 4, lr2 = r & 7, hf = (r >> 3) & 1;
                        float* qp = g_qp + ((size_t)(bh * NQ + qt)) * 8192 + w * 1024;
                        qp[(d  >> 3) * 128 + (lr2 * 4 + (d  & 3)) * 4 + hf + 2 * ((d  >> 2) & 1)]
                            = tf32f(v0 * SCALE);
                        qp[(d1 >> 3) * 128 + (lr2 * 4 + (d1 & 3)) * 4 + hf + 2 * ((d1 >> 2) & 1)]
                            = tf32f(v1 * SCALE);
                    } else if (t == 1) {
                        *(float2*)&g_k[((size_t)bh * LL + l) * DD + d] =
                            make_float2(v0, v1);
                        int kb = l >> 6, n = l & 63;
                        float* kp = g_kp + ((size_t)(bh * NK + kb)) * 4096 + n * 8;
                        kp[(d  >> 3) * 512 + (d  & 3) * 2 + ((d  >> 2) & 1)] = tf32f(v0);
                        kp[(d1 >> 3) * 512 + (d1 & 3) * 2 + ((d1 >> 2) & 1)] = tf32f(v1);
                    } else {
                        int kb = l >> 6, k64 = l & 63;
                        float* vp = g_vp + ((size_t)(bh * NK + kb)) * 4096
                                  + (k64 >> 3) * 512 + (k64 & 3) * 2 + ((k64 >> 2) & 1);
                        vp[d  * 8] = tf32f(v0);
                        vp[d1 * 8] = tf32f(v1);
                    }
                } else {
                    *(float2*)&out[(size_t)row * N + col] = make_float2(v0, v1);
                }
            }
        }
    }
}

// ---------------------------------------------------------------------------
// Kernel 2a: per-block mean + min-cosine.
// ---------------------------------------------------------------------------
__global__ void __launch_bounds__(256) meansim_kernel() {
    int bh = blockIdx.y;
    int j  = blockIdx.x;
    bool isQ = j < NQ;
    int blk  = isQ ? j : j - NQ;
    int rows = isQ ? 128 : 64;
    const float* base = (isQ ? g_q : g_k) + (size_t)bh * LL * DD + (size_t)blk * rows * DD;
    __shared__ float psum[256];
    __shared__ float mean[64];
    __shared__ float nrm;
    __shared__ float simv;
    int tid = threadIdx.x;
    if (tid == 0) simv = 1e30f;

    {
        int d = tid & 63, rg = tid >> 6;
        float acc = 0.f;
        for (int r = rg; r < rows; r += 4) acc += base[r * DD + d];
        psum[tid] = acc;
    }
    __syncthreads();
    if (tid < 64) {
        float m = (psum[tid] + psum[tid + 64] + psum[tid + 128] + psum[tid + 192])
                  * (1.f / rows);
        mean[tid] = m;
        float* gm = isQ ? &g_qm[bh][blk][0] : &g_km[bh][blk][0];
        gm[tid] = m;
    }
    __syncthreads();
    if (tid < 32) {
        float s = mean[tid] * mean[tid] + mean[tid + 32] * mean[tid + 32];
        #pragma unroll
        for (int o = 16; o >= 1; o >>= 1) s += __shfl_xor_sync(0xffffffffu, s, o);
        if (tid == 0) nrm = sqrtf(s);
    }
    __syncthreads();
    float mnorm = nrm;

    float cosv;
    if (isQ) {
        int row = tid >> 1, half = tid & 1;
        const float* p  = base + row * DD + half * 32;
        const float* mp = mean + half * 32;
        float dot = 0.f, nn = 0.f;
        #pragma unroll
        for (int d = 0; d < 32; d++) { float v = p[d]; dot += v * mp[d]; nn += v * v; }
        dot += __shfl_xor_sync(0xffffffffu, dot, 1);
        nn  += __shfl_xor_sync(0xffffffffu, nn,  1);
        cosv = dot / ((sqrtf(nn) + 1e-6f) * (mnorm + 1e-6f));
    } else {
        int row = tid >> 2, qd = tid & 3;
        const float* p  = base + row * DD + qd * 16;
        const float* mp = mean + qd * 16;
        float dot = 0.f, nn = 0.f;
        #pragma unroll
        for (int d = 0; d < 16; d++) { float v = p[d]; dot += v * mp[d]; nn += v * v; }
        dot += __shfl_xor_sync(0xffffffffu, dot, 1);
        dot += __shfl_xor_sync(0xffffffffu, dot, 2);
        nn  += __shfl_xor_sync(0xffffffffu, nn,  1);
        nn  += __shfl_xor_sync(0xffffffffu, nn,  2);
        cosv = dot / ((sqrtf(nn) + 1e-6f) * (mnorm + 1e-6f));
    }
    #pragma unroll
    for (int o = 16; o >= 1; o >>= 1)
        cosv = fminf(cosv, __shfl_xor_sync(0xffffffffu, cosv, o));
    if ((tid & 31) == 0) atomicMinFloat(&simv, cosv);
    __syncthreads();
    if (tid == 0) {
        if (isQ) g_qsim[bh][blk] = simv; else g_ksim[bh][blk] = simv;
    }
}

// ---------------------------------------------------------------------------
// Kernel 2b: pooled softmax + CDF keep -> block mask.
// ---------------------------------------------------------------------------
__global__ void __launch_bounds__(256) mask_kernel() {
    int bh = blockIdx.x;
    __shared__ float pooled[NQ][NK];
    __shared__ float qs[NQ], kss[NK];
    int tid = threadIdx.x;
    if (tid < NQ) qs[tid]  = g_qsim[bh][tid];
    if (tid < NK) kss[tid] = g_ksim[bh][tid];
    for (int e = tid; e < NQ * NK; e += 256) {
        int qi = e >> 5, ki = e & 31;
        const float* a = g_qm[bh][qi];
        const float* b = g_km[bh][ki];
        float dot = 0.f;
        #pragma unroll
        for (int d = 0; d < DD; d++) dot += a[d] * b[d];
        pooled[qi][ki] = dot * SCALE;
    }
    __syncthreads();
    if (tid < NQ) {
        float vals[NK]; int idx[NK];
        float mx = -CUDART_INF_F;
        for (int i = 0; i < NK; i++) mx = fmaxf(mx, pooled[tid][i]);
        float sum = 0.f;
        for (int i = 0; i < NK; i++) { vals[i] = expf(pooled[tid][i] - mx); sum += vals[i]; }
        float inv = 1.f / sum;
        for (int i = 0; i < NK; i++) { vals[i] *= inv; idx[i] = i; }
        for (int i = 1; i < NK; i++) {
            float kv = vals[i]; int ki = idx[i];
            int j = i - 1;
            while (j >= 0 && vals[j] < kv) { vals[j+1] = vals[j]; idx[j+1] = idx[j]; j--; }
            vals[j+1] = kv; idx[j+1] = ki;
        }
        unsigned keep = 0u;
        float csum = 0.f;
        for (int i = 0; i < NK; i++) {
            if (csum < CDFTH) keep |= (1u << idx[i]);
            csum += vals[i];
        }
        bool qself = qs[tid] > SIMTH;
        int* mrow = g_mask + (bh * NQ + tid) * NK;
        for (int ki = 0; ki < NK; ki++) {
            bool kself = kss[ki] > SIMTH;
            mrow[ki] = (((keep >> ki) & 1u) || !qself || !kself) ? 1 : 0;
        }
    }
}

// ---------------------------------------------------------------------------
// Kernel 3: block-sparse flash attention, tf32 mma, fragment-packed operands.
// R10 phase structure (S -> softmax -> batched PV) + double-buffered K/V
// prefetch; Pp shrunk to 4 slices, PV runs in two 4-slice batches.
// grid = (16 q-tiles of 128 rows, 16 bh), 256 threads = 8 warps.
// smem: Qp[8192] | K0/K1[4096 ea] | V0/V1[4096 ea] | Pp[8 w][512]
//     = 28672 floats = 112 KB -> 2 CTAs/SM (224 <= 228 KB).
// ---------------------------------------------------------------------------
#define ATT_QP_FL 8192
#define ATT_KV_FL 4096
#define ATT_SMEM_FLOATS (ATT_QP_FL + 4*ATT_KV_FL + 8*512)   // 28672
#define ATT_SMEM_BYTES  (ATT_SMEM_FLOATS * 4)               // 114688

__global__ void __launch_bounds__(256, 2) attn_tf32() {
    const int qb = blockIdx.x;
    const int bh = blockIdx.y;
    const int b = bh >> 3, h = bh & 7;
    const int tid  = threadIdx.x;
    const int wid  = tid >> 5;
    const int lane = tid & 31;
    const int lr = lane >> 2;
    const int lc = lane & 3;

    float* Qp   = sm_dyn;                                   // [8 w][8 kk][32 lane][4]
    float* Kbuf = sm_dyn + ATT_QP_FL;                       // [2][4096]
    float* Vbuf = Kbuf + 2 * ATT_KV_FL;                     // [2][4096]
    float* PpW  = Vbuf + 2 * ATT_KV_FL + wid * 512;         // [4 slice][2 c2][32 L][2]
    unsigned sbase  = (unsigned)__cvta_generic_to_shared(sm_dyn);
    unsigned kbuf_u = sbase + (unsigned)ATT_QP_FL * 4u;
    unsigned vbuf_u = kbuf_u + 2u * ATT_KV_FL * 4u;

    __shared__ int s_list[NK];
    __shared__ int s_nk;

    // Stage Q fragments (precomputed, tf32*scale): 8192 floats
    const float* qsrc = g_qp + ((size_t)(bh * NQ + qb)) * 8192;
    #pragma unroll
    for (int i = 0; i < 8; i++)
        cp16(sbase + (unsigned)(tid + i * 256) * 16u, qsrc + (tid + i * 256) * 4);
    asm volatile("cp.async.commit_group;");

    // Kept-block list
    const int* mrow = g_mask + (bh * NQ + qb) * NK;
    if (tid == 0) {
        int c = 0;
        for (int i = 0; i < NK; i++) if (mrow[i]) s_list[c++] = i;
        s_nk = c;
    }
    __syncthreads();
    const int nkeep = s_nk;

    const float* kgp = g_kp + (size_t)bh * NK * 4096;
    const float* vgp = g_vp + (size_t)bh * NK * 4096;

    auto stage_kv = [&](int buf, int kb) {
        const float* ks = kgp + (size_t)kb * 4096;
        const float* vs = vgp + (size_t)kb * 4096;
        unsigned ko = kbuf_u + (unsigned)(buf * ATT_KV_FL) * 4u;
        unsigned vo = vbuf_u + (unsigned)(buf * ATT_KV_FL) * 4u;
        #pragma unroll
        for (int i = 0; i < 4; i++) {
            unsigned off = (unsigned)(tid + i * 256) * 16u;
            cp16(ko + off, ks + (tid + i * 256) * 4);
            cp16(vo + off, vs + (tid + i * 256) * 4);
        }
        asm volatile("cp.async.commit_group;");
    };

    stage_kv(0, s_list[0]);

    float o[8][4];
    #pragma unroll
    for (int nt = 0; nt < 8; nt++)
        #pragma unroll
        for (int j = 0; j < 4; j++) o[nt][j] = 0.f;
    float m0r = -CUDART_INF_F, m1r = -CUDART_INF_F;
    float l0 = 0.f, l1 = 0.f;

    const float* QpW = Qp + wid * 1024;

    for (int i = 0; i < nkeep; i++) {
        int buf = i & 1;
        asm volatile("cp.async.wait_group 0;");
        __syncthreads();               // staged data visible; prev iter reads done
        if (i + 1 < nkeep) stage_kv(buf ^ 1, s_list[i + 1]);

        const float* Kp = Kbuf + buf * ATT_KV_FL;
        const float* Vp = Vbuf + buf * ATT_KV_FL;

        // ---- S = Q K^T (batched, as in R10) ----
        float sc[8][4];
        #pragma unroll
        for (int nt = 0; nt < 8; nt++)
            #pragma unroll
            for (int j = 0; j < 4; j++) sc[nt][j] = 0.f;

        #pragma unroll
        for (int kk = 0; kk < 8; kk++) {
            float4 av = *(const float4*)(QpW + kk * 128 + lane * 4);
            unsigned a0 = __float_as_uint(av.x), a1 = __float_as_uint(av.y);
            unsigned a2 = __float_as_uint(av.z), a3 = __float_as_uint(av.w);
            const float* kbase = Kp + kk * 512 + lr * 8 + lc * 2;
            #pragma unroll
            for (int nt = 0; nt < 8; nt++) {
                float2 bv = *(const float2*)(kbase + nt * 64);
                mma_tf32(sc[nt], a0, a1, a2, a3,
                         __float_as_uint(bv.x), __float_as_uint(bv.y));
            }
        }

        // ---- Online softmax maxes / rescale (rows lr, lr+8) ----
        float rl = -CUDART_INF_F, rh = -CUDART_INF_F;
        #pragma unroll
        for (int nt = 0; nt < 8; nt++) {
            rl = fmaxf(rl, fmaxf(sc[nt][0], sc[nt][1]));
            rh = fmaxf(rh, fmaxf(sc[nt][2], sc[nt][3]));
        }
        rl = fmaxf(rl, __shfl_xor_sync(0xffffffffu, rl, 1));
        rl = fmaxf(rl, __shfl_xor_sync(0xffffffffu, rl, 2));
        rh = fmaxf(rh, __shfl_xor_sync(0xffffffffu, rh, 1));
        rh = fmaxf(rh, __shfl_xor_sync(0xffffffffu, rh, 2));
        float mn0 = fmaxf(m0r, rl), mn1 = fmaxf(m1r, rh);
        float c0 = __expf(m0r - mn0), c1 = __expf(m1r - mn1);
        #pragma unroll
        for (int nt = 0; nt < 8; nt++) {
            o[nt][0] *= c0; o[nt][1] *= c0;
            o[nt][2] *= c1; o[nt][3] *= c1;
        }

        // ---- PV in two 4-slice batches ----
        float s0 = 0.f, s1 = 0.f;
        #pragma unroll
        for (int ph = 0; ph < 2; ph++) {
            int base_nt = ph * 4;
            if (ph) __syncwarp();     // phase-A reads done before overwrite
            #pragma unroll
            for (int j = 0; j < 4; j++) {
                int nt = base_nt + j;
                float p0 = __expf(sc[nt][0] - mn0);
                float p1 = __expf(sc[nt][1] - mn0);
                float p2 = __expf(sc[nt][2] - mn1);
                float p3 = __expf(sc[nt][3] - mn1);
                s0 += p0 + p1; s1 += p2 + p3;
                float* Pb = PpW + j * 128;
                *(float2*)(Pb +      lane * 2) = make_float2(tf32f(p0), tf32f(p2));
                *(float2*)(Pb + 64 + lane * 2) = make_float2(tf32f(p1), tf32f(p3));
            }
            __syncwarp();
            #pragma unroll
            for (int j = 0; j < 4; j++) {
                int kk = base_nt + j;
                const float* pb = PpW + j * 128 + (lc & 1) * 64
                                + (lr * 4 + (lc >> 1)) * 2;
                float2 A01 = *(const float2*)pb;        // P[lr][8kk+lc], P[lr+8][..]
                float2 A23 = *(const float2*)(pb + 4);  // cols +4
                unsigned a0 = __float_as_uint(A01.x), a1 = __float_as_uint(A01.y);
                unsigned a2 = __float_as_uint(A23.x), a3 = __float_as_uint(A23.y);
                const float* vbase = Vp + kk * 512 + lr * 8 + lc * 2;
                #pragma unroll
                for (int nt2 = 0; nt2 < 8; nt2++) {
                    float2 bv = *(const float2*)(vbase + nt2 * 64);
                    mma_tf32(o[nt2], a0, a1, a2, a3,
                             __float_as_uint(bv.x), __float_as_uint(bv.y));
                }
            }
        }
        s0 += __shfl_xor_sync(0xffffffffu, s0, 1);
        s0 += __shfl_xor_sync(0xffffffffu, s0, 2);
        s1 += __shfl_xor_sync(0xffffffffu, s1, 1);
        s1 += __shfl_xor_sync(0xffffffffu, s1, 2);
        l0 = l0 * c0 + s0;
        l1 = l1 * c1 + s1;
        m0r = mn0; m1r = mn1;
    }

    // Epilogue: normalize and scatter to g_o
    float inv0 = 1.f / l0, inv1 = 1.f / l1;
    int r0 = qb * 128 + wid * 16 + lr;
    float* og = g_o + (size_t)b * LL * CC + h * DD;
    #pragma unroll
    for (int nt = 0; nt < 8; nt++) {
        float2 w0 = make_float2(o[nt][0] * inv0, o[nt][1] * inv0);
        float2 w1 = make_float2(o[nt][2] * inv1, o[nt][3] * inv1);
        *(float2*)&og[(size_t)(r0    ) * CC + nt * 8 + 2 * lc] = w0;
        *(float2*)&og[(size_t)(r0 + 8) * CC + nt * 8 + 2 * lc] = w1;
    }
}

// ---------------------------------------------------------------------------
extern "C" void kernel_launch(void* const* d_in, const int* in_sizes, int n_in,
                              void* d_out, int out_size) {
    const float* x     = (const float*)d_in[0];
    const float* Wqkv  = (const float*)d_in[1];
    const float* bqkv  = (const float*)d_in[2];
    const float* Wproj = (const float*)d_in[3];
    const float* bproj = (const float*)d_in[4];
    float* out = (float*)d_out;

    cudaFuncSetAttribute(attn_tf32, cudaFuncAttributeMaxDynamicSharedMemorySize,
                         ATT_SMEM_BYTES);
    cudaFuncSetAttribute(gemm_tf32<NQKV, true>,
                         cudaFuncAttributeMaxDynamicSharedMemorySize, GEMM_SMEM_BYTES);
    cudaFuncSetAttribute(gemm_tf32<CC, false>,
                         cudaFuncAttributeMaxDynamicSharedMemorySize, GEMM_SMEM_BYTES);

    gemm_tf32<NQKV, true><<<dim3(NQKV / 64, MM / 128), 256, GEMM_SMEM_BYTES>>>(
        x, Wqkv, bqkv, nullptr);
    meansim_kernel<<<dim3(NQ + NK, BB * HH), 256>>>();
    mask_kernel<<<BB * HH, 256>>>();
    attn_tf32<<<dim3(NQ, BB * HH), 256, ATT_SMEM_BYTES>>>();
    gemm_tf32<CC, false><<<dim3(CC / 64, MM / 128), 256, GEMM_SMEM_BYTES>>>(
        nullptr, Wproj, bproj, out);
}

// round 13
// speedup vs baseline: 1.6236x; 1.0529x over previous
#include <cuda_runtime.h>
#include <cuda_bf16.h>
#include <math_constants.h>

// Problem constants
#define BB   2
#define LL   2048
#define CC   512
#define HH   8
#define DD   64
#define MM   (BB*LL)          // 4096 rows
#define NQKV (3*CC)           // 1536
#define NQ   16               // L/128 (mask Q-block granularity)
#define NK   32               // L/64
#define SCALE 0.125f          // D^-0.5
#define SIMTH 0.6f
#define CDFTH 0.98f

// Scratch (allocation-free rule -> device globals)
__device__ float g_q[BB*HH*LL*DD];        // raw [B,H,L,D] (meansim)
__device__ float g_k[BB*HH*LL*DD];        // raw [B,H,L,D] (meansim)
__device__ float g_qp[BB*HH*NQ*8192];     // Q A-fragments, tf32(q*SCALE)  (128x64)
__device__ float g_kp[BB*HH*NK*4096];     // K B-frag pairs, tf32          (64x64)
__device__ float g_vp[BB*HH*NK*4096];     // V B-frag pairs, tf32          (64x64)
__device__ float g_o[BB*LL*CC];           // [B,L,C]
__device__ int   g_mask[BB*HH*NQ*NK];     // 1 = keep block
__device__ float g_qm[BB*HH][NQ][DD];
__device__ float g_km[BB*HH][NK][DD];
__device__ float g_qsim[BB*HH][NQ];
__device__ float g_ksim[BB*HH][NK];

__device__ __forceinline__ unsigned f2tf32(float x) {
    unsigned r;
    asm("cvt.rna.tf32.f32 %0, %1;" : "=r"(r) : "f"(x));
    return r;
}
__device__ __forceinline__ float tf32f(float x) {
    return __uint_as_float(f2tf32(x));
}

__device__ __forceinline__ void mma_tf32(float c[4],
                                         unsigned a0, unsigned a1, unsigned a2, unsigned a3,
                                         unsigned b0, unsigned b1) {
    asm volatile(
        "mma.sync.aligned.m16n8k8.row.col.f32.tf32.tf32.f32 "
        "{%0,%1,%2,%3}, {%4,%5,%6,%7}, {%8,%9}, {%0,%1,%2,%3};"
        : "+f"(c[0]), "+f"(c[1]), "+f"(c[2]), "+f"(c[3])
        : "r"(a0), "r"(a1), "r"(a2), "r"(a3), "r"(b0), "r"(b1));
}

__device__ __forceinline__ void cp16(unsigned smem_dst, const void* gsrc) {
    asm volatile("cp.async.ca.shared.global [%0], [%1], 16;"
                 :: "r"(smem_dst), "l"(gsrc));
}

__device__ __forceinline__ void atomicMinFloat(float* addr, float val) {
    int* ia = (int*)addr;
    int old = *ia;
    while (__int_as_float(old) > val) {
        int assumed = old;
        old = atomicCAS(ia, assumed, __float_as_int(val));
        if (old == assumed) break;
    }
}

// ---------------------------------------------------------------------------
// tf32 tensor-core GEMM: C[M,N] = A[M,K=512] @ B[K,N] + bias
// 128x64 tile, 256 threads = 8 warps (4M x 2N), cp.async double-buffered.
// SCATTER=true: writes raw q/k + fragment-packed qp/kp/vp.
// ---------------------------------------------------------------------------
#define GA_ST 36
#define GB_ST 72
#define GA_FL (128*GA_ST)          // 4608
#define GB_FL (32*GB_ST)           // 2304
#define GEMM_SMEM_FLOATS (2*GA_FL + 2*GB_FL)
#define GEMM_SMEM_BYTES  (GEMM_SMEM_FLOATS*4)

extern __shared__ float sm_dyn[];

template<int N, bool SCATTER>
__global__ void __launch_bounds__(256) gemm_tf32(const float* __restrict__ A,
                                                 const float* __restrict__ Bw,
                                                 const float* __restrict__ bias,
                                                 float* __restrict__ out) {
    const int K = CC;
    const float* Ap = SCATTER ? A : (const float*)g_o;
    int m0 = blockIdx.y * 128, n0 = blockIdx.x * 64;
    float* Asm = sm_dyn;
    float* Bsm = sm_dyn + 2 * GA_FL;
    unsigned sbase = (unsigned)__cvta_generic_to_shared(sm_dyn);
    int tid = threadIdx.x;
    int wid = tid >> 5, lane = tid & 31;
    int lr = lane >> 2, lc = lane & 3;
    int warp_m = wid & 3, warp_n = wid >> 2;

    float c[2][4][4] = {};

    auto stage = [&](int buf, int k0) {
        unsigned a_s = sbase + (unsigned)(buf * GA_FL) * 4u;
        unsigned b_s = sbase + (unsigned)(2 * GA_FL + buf * GB_FL) * 4u;
        #pragma unroll
        for (int i = 0; i < 4; i++) {
            int f4 = tid + i * 256;
            int r = f4 >> 3, cg = f4 & 7;
            cp16(a_s + (unsigned)(r * GA_ST + cg * 4) * 4u,
                 &Ap[(size_t)(m0 + r) * K + k0 + cg * 4]);
        }
        #pragma unroll
        for (int i = 0; i < 2; i++) {
            int f4 = tid + i * 256;
            int r = f4 >> 4, ng = f4 & 15;
            cp16(b_s + (unsigned)(r * GB_ST + ng * 4) * 4u,
                 &Bw[(size_t)(k0 + r) * N + n0 + ng * 4]);
        }
        asm volatile("cp.async.commit_group;");
    };

    stage(0, 0);
    const int NCHUNK = K / 32;
    for (int ch = 0; ch < NCHUNK; ch++) {
        int buf = ch & 1;
        if (ch < NCHUNK - 1) {
            stage(buf ^ 1, (ch + 1) * 32);
            asm volatile("cp.async.wait_group 1;");
        } else {
            asm volatile("cp.async.wait_group 0;");
        }
        __syncthreads();

        const float* Aw = Asm + buf * GA_FL + (warp_m * 32) * GA_ST;
        const float* Bb = Bsm + buf * GB_FL;
        #pragma unroll
        for (int kk = 0; kk < 4; kk++) {
            int kf = kk * 8;
            unsigned a[2][4];
            #pragma unroll
            for (int mt = 0; mt < 2; mt++) {
                a[mt][0] = f2tf32(Aw[(mt * 16 + lr    ) * GA_ST + kf + lc    ]);
                a[mt][1] = f2tf32(Aw[(mt * 16 + lr + 8) * GA_ST + kf + lc    ]);
                a[mt][2] = f2tf32(Aw[(mt * 16 + lr    ) * GA_ST + kf + lc + 4]);
                a[mt][3] = f2tf32(Aw[(mt * 16 + lr + 8) * GA_ST + kf + lc + 4]);
            }
            unsigned bf[4][2];
            #pragma unroll
            for (int nt = 0; nt < 4; nt++) {
                int nn = warp_n * 32 + nt * 8 + lr;
                bf[nt][0] = f2tf32(Bb[(kf + lc    ) * GB_ST + nn]);
                bf[nt][1] = f2tf32(Bb[(kf + lc + 4) * GB_ST + nn]);
            }
            #pragma unroll
            for (int mt = 0; mt < 2; mt++)
                #pragma unroll
                for (int nt = 0; nt < 4; nt++)
                    mma_tf32(c[mt][nt], a[mt][0], a[mt][1], a[mt][2], a[mt][3],
                             bf[nt][0], bf[nt][1]);
        }
        __syncthreads();
    }

    // Epilogue
    int t = n0 >> 9;   // uniform per CTA when SCATTER
    #pragma unroll
    for (int mt = 0; mt < 2; mt++) {
        #pragma unroll
        for (int half = 0; half < 2; half++) {
            int row = m0 + warp_m * 32 + mt * 16 + lr + half * 8;
            #pragma unroll
            for (int nt = 0; nt < 4; nt++) {
                int col = n0 + warp_n * 32 + nt * 8 + 2 * lc;
                float v0 = c[mt][nt][half * 2 + 0] + bias[col];
                float v1 = c[mt][nt][half * 2 + 1] + bias[col + 1];
                if (SCATTER) {
                    int b = row >> 11, l = row & 2047;
                    int h = (col & 511) >> 6;
                    int d = col & 63, d1 = d + 1;
                    int bh = b * HH + h;
                    if (t == 0) {
                        *(float2*)&g_q[((size_t)bh * LL + l) * DD + d] =
                            make_float2(v0, v1);
                        int qt = l >> 7, r = l & 127;
                        int w = r >> 4, lr2 = r & 7, hf = (r >> 3) & 1;
                        float* qp = g_qp + ((size_t)(bh * NQ + qt)) * 8192 + w * 1024;
                        qp[(d  >> 3) * 128 + (lr2 * 4 + (d  & 3)) * 4 + hf + 2 * ((d  >> 2) & 1)]
                            = tf32f(v0 * SCALE);
                        qp[(d1 >> 3) * 128 + (lr2 * 4 + (d1 & 3)) * 4 + hf + 2 * ((d1 >> 2) & 1)]
                            = tf32f(v1 * SCALE);
                    } else if (t == 1) {
                        *(float2*)&g_k[((size_t)bh * LL + l) * DD + d] =
                            make_float2(v0, v1);
                        int kb = l >> 6, n = l & 63;
                        float* kp = g_kp + ((size_t)(bh * NK + kb)) * 4096 + n * 8;
                        kp[(d  >> 3) * 512 + (d  & 3) * 2 + ((d  >> 2) & 1)] = tf32f(v0);
                        kp[(d1 >> 3) * 512 + (d1 & 3) * 2 + ((d1 >> 2) & 1)] = tf32f(v1);
                    } else {
                        int kb = l >> 6, k64 = l & 63;
                        float* vp = g_vp + ((size_t)(bh * NK + kb)) * 4096
                                  + (k64 >> 3) * 512 + (k64 & 3) * 2 + ((k64 >> 2) & 1);
                        vp[d  * 8] = tf32f(v0);
                        vp[d1 * 8] = tf32f(v1);
                    }
                } else {
                    *(float2*)&out[(size_t)row * N + col] = make_float2(v0, v1);
                }
            }
        }
    }
}

// ---------------------------------------------------------------------------
// Kernel 2a: per-block mean + min-cosine.
// ---------------------------------------------------------------------------
__global__ void __launch_bounds__(256) meansim_kernel() {
    int bh = blockIdx.y;
    int j  = blockIdx.x;
    bool isQ = j < NQ;
    int blk  = isQ ? j : j - NQ;
    int rows = isQ ? 128 : 64;
    const float* base = (isQ ? g_q : g_k) + (size_t)bh * LL * DD + (size_t)blk * rows * DD;
    __shared__ float psum[256];
    __shared__ float mean[64];
    __shared__ float nrm;
    __shared__ float simv;
    int tid = threadIdx.x;
    if (tid == 0) simv = 1e30f;

    {
        int d = tid & 63, rg = tid >> 6;
        float acc = 0.f;
        for (int r = rg; r < rows; r += 4) acc += base[r * DD + d];
        psum[tid] = acc;
    }
    __syncthreads();
    if (tid < 64) {
        float m = (psum[tid] + psum[tid + 64] + psum[tid + 128] + psum[tid + 192])
                  * (1.f / rows);
        mean[tid] = m;
        float* gm = isQ ? &g_qm[bh][blk][0] : &g_km[bh][blk][0];
        gm[tid] = m;
    }
    __syncthreads();
    if (tid < 32) {
        float s = mean[tid] * mean[tid] + mean[tid + 32] * mean[tid + 32];
        #pragma unroll
        for (int o = 16; o >= 1; o >>= 1) s += __shfl_xor_sync(0xffffffffu, s, o);
        if (tid == 0) nrm = sqrtf(s);
    }
    __syncthreads();
    float mnorm = nrm;

    float cosv;
    if (isQ) {
        int row = tid >> 1, half = tid & 1;
        const float* p  = base + row * DD + half * 32;
        const float* mp = mean + half * 32;
        float dot = 0.f, nn = 0.f;
        #pragma unroll
        for (int d = 0; d < 32; d++) { float v = p[d]; dot += v * mp[d]; nn += v * v; }
        dot += __shfl_xor_sync(0xffffffffu, dot, 1);
        nn  += __shfl_xor_sync(0xffffffffu, nn,  1);
        cosv = dot / ((sqrtf(nn) + 1e-6f) * (mnorm + 1e-6f));
    } else {
        int row = tid >> 2, qd = tid & 3;
        const float* p  = base + row * DD + qd * 16;
        const float* mp = mean + qd * 16;
        float dot = 0.f, nn = 0.f;
        #pragma unroll
        for (int d = 0; d < 16; d++) { float v = p[d]; dot += v * mp[d]; nn += v * v; }
        dot += __shfl_xor_sync(0xffffffffu, dot, 1);
        dot += __shfl_xor_sync(0xffffffffu, dot, 2);
        nn  += __shfl_xor_sync(0xffffffffu, nn,  1);
        nn  += __shfl_xor_sync(0xffffffffu, nn,  2);
        cosv = dot / ((sqrtf(nn) + 1e-6f) * (mnorm + 1e-6f));
    }
    #pragma unroll
    for (int o = 16; o >= 1; o >>= 1)
        cosv = fminf(cosv, __shfl_xor_sync(0xffffffffu, cosv, o));
    if ((tid & 31) == 0) atomicMinFloat(&simv, cosv);
    __syncthreads();
    if (tid == 0) {
        if (isQ) g_qsim[bh][blk] = simv; else g_ksim[bh][blk] = simv;
    }
}

// ---------------------------------------------------------------------------
// Kernel 2b: pooled softmax + CDF keep -> block mask.
// ---------------------------------------------------------------------------
__global__ void __launch_bounds__(256) mask_kernel() {
    int bh = blockIdx.x;
    __shared__ float pooled[NQ][NK];
    __shared__ float qs[NQ], kss[NK];
    int tid = threadIdx.x;
    if (tid < NQ) qs[tid]  = g_qsim[bh][tid];
    if (tid < NK) kss[tid] = g_ksim[bh][tid];
    for (int e = tid; e < NQ * NK; e += 256) {
        int qi = e >> 5, ki = e & 31;
        const float* a = g_qm[bh][qi];
        const float* b = g_km[bh][ki];
        float dot = 0.f;
        #pragma unroll
        for (int d = 0; d < DD; d++) dot += a[d] * b[d];
        pooled[qi][ki] = dot * SCALE;
    }
    __syncthreads();
    if (tid < NQ) {
        float vals[NK]; int idx[NK];
        float mx = -CUDART_INF_F;
        for (int i = 0; i < NK; i++) mx = fmaxf(mx, pooled[tid][i]);
        float sum = 0.f;
        for (int i = 0; i < NK; i++) { vals[i] = expf(pooled[tid][i] - mx); sum += vals[i]; }
        float inv = 1.f / sum;
        for (int i = 0; i < NK; i++) { vals[i] *= inv; idx[i] = i; }
        for (int i = 1; i < NK; i++) {
            float kv = vals[i]; int ki = idx[i];
            int j = i - 1;
            while (j >= 0 && vals[j] < kv) { vals[j+1] = vals[j]; idx[j+1] = idx[j]; j--; }
            vals[j+1] = kv; idx[j+1] = ki;
        }
        unsigned keep = 0u;
        float csum = 0.f;
        for (int i = 0; i < NK; i++) {
            if (csum < CDFTH) keep |= (1u << idx[i]);
            csum += vals[i];
        }
        bool qself = qs[tid] > SIMTH;
        int* mrow = g_mask + (bh * NQ + tid) * NK;
        for (int ki = 0; ki < NK; ki++) {
            bool kself = kss[ki] > SIMTH;
            mrow[ki] = (((keep >> ki) & 1u) || !qself || !kself) ? 1 : 0;
        }
    }
}

// ---------------------------------------------------------------------------
// Kernel 3: block-sparse flash attention, tf32 mma, fragment-packed operands.
// 4 warps x 32 q-rows (two m16 A-frags per warp) -> every K/V B-fragment
// LDS feeds 2 mma; K/V double-buffered cp.async prefetch; PV in two
// 4-slice batches.
// grid = (16 q-tiles of 128 rows, 16 bh), 128 threads = 4 warps.
// smem: Qp[8192] | K0/K1[4096 ea] | V0/V1[4096 ea] | Pp[4 w][1024]
//     = 28672 floats = 112 KB -> 2 CTAs/SM.
// ---------------------------------------------------------------------------
#define ATT_QP_FL 8192
#define ATT_KV_FL 4096
#define ATT_SMEM_FLOATS (ATT_QP_FL + 4*ATT_KV_FL + 4*1024)  // 28672
#define ATT_SMEM_BYTES  (ATT_SMEM_FLOATS * 4)               // 114688

__global__ void __launch_bounds__(128, 2) attn_tf32() {
    const int qb = blockIdx.x;
    const int bh = blockIdx.y;
    const int b = bh >> 3, h = bh & 7;
    const int tid  = threadIdx.x;
    const int wid  = tid >> 5;          // 0..3, warp owns rows wid*32..wid*32+31
    const int lane = tid & 31;
    const int lr = lane >> 2;
    const int lc = lane & 3;

    float* Qp   = sm_dyn;                                   // [8 chunk][8 kk][32 lane][4]
    float* Kbuf = sm_dyn + ATT_QP_FL;                       // [2][4096]
    float* Vbuf = Kbuf + 2 * ATT_KV_FL;                     // [2][4096]
    float* PpW  = Vbuf + 2 * ATT_KV_FL + wid * 1024;        // [4 slice][2 g][2 c2][32 L][2]
    unsigned sbase  = (unsigned)__cvta_generic_to_shared(sm_dyn);
    unsigned kbuf_u = sbase + (unsigned)ATT_QP_FL * 4u;
    unsigned vbuf_u = kbuf_u + 2u * ATT_KV_FL * 4u;

    __shared__ int s_list[NK];
    __shared__ int s_nk;

    // Stage Q fragments (precomputed, tf32*scale): 8192 floats / 128 threads
    const float* qsrc = g_qp + ((size_t)(bh * NQ + qb)) * 8192;
    #pragma unroll
    for (int i = 0; i < 16; i++)
        cp16(sbase + (unsigned)(tid + i * 128) * 16u, qsrc + (tid + i * 128) * 4);
    asm volatile("cp.async.commit_group;");

    // Kept-block list
    const int* mrow = g_mask + (bh * NQ + qb) * NK;
    if (tid == 0) {
        int c = 0;
        for (int i = 0; i < NK; i++) if (mrow[i]) s_list[c++] = i;
        s_nk = c;
    }
    __syncthreads();
    const int nkeep = s_nk;

    const float* kgp = g_kp + (size_t)bh * NK * 4096;
    const float* vgp = g_vp + (size_t)bh * NK * 4096;

    auto stage_kv = [&](int buf, int kb) {
        const float* ks = kgp + (size_t)kb * 4096;
        const float* vs = vgp + (size_t)kb * 4096;
        unsigned ko = kbuf_u + (unsigned)(buf * ATT_KV_FL) * 4u;
        unsigned vo = vbuf_u + (unsigned)(buf * ATT_KV_FL) * 4u;
        #pragma unroll
        for (int i = 0; i < 8; i++) {
            unsigned off = (unsigned)(tid + i * 128) * 16u;
            cp16(ko + off, ks + (tid + i * 128) * 4);
            cp16(vo + off, vs + (tid + i * 128) * 4);
        }
        asm volatile("cp.async.commit_group;");
    };

    stage_kv(0, s_list[0]);

    float o[2][8][4];
    #pragma unroll
    for (int g = 0; g < 2; g++)
        #pragma unroll
        for (int nt = 0; nt < 8; nt++)
            #pragma unroll
            for (int j = 0; j < 4; j++) o[g][nt][j] = 0.f;
    float m[4] = {-CUDART_INF_F, -CUDART_INF_F, -CUDART_INF_F, -CUDART_INF_F};
    float l[4] = {0.f, 0.f, 0.f, 0.f};

    const float* QwA = Qp + (2 * wid    ) * 1024;   // rows wid*32 .. +15
    const float* QwB = Qp + (2 * wid + 1) * 1024;   // rows wid*32+16 .. +31

    for (int i = 0; i < nkeep; i++) {
        int buf = i & 1;
        asm volatile("cp.async.wait_group 0;");
        __syncthreads();               // staged data visible; prev iter reads done
        if (i + 1 < nkeep) stage_kv(buf ^ 1, s_list[i + 1]);

        const float* Kp = Kbuf + buf * ATT_KV_FL;
        const float* Vp = Vbuf + buf * ATT_KV_FL;

        // ---- S = Q K^T : 32 rows x 64 kpos per warp ----
        float sc[2][8][4];
        #pragma unroll
        for (int g = 0; g < 2; g++)
            #pragma unroll
            for (int nt = 0; nt < 8; nt++)
                #pragma unroll
                for (int j = 0; j < 4; j++) sc[g][nt][j] = 0.f;

        #pragma unroll
        for (int kk = 0; kk < 8; kk++) {
            float4 avA = *(const float4*)(QwA + kk * 128 + lane * 4);
            float4 avB = *(const float4*)(QwB + kk * 128 + lane * 4);
            unsigned aA0 = __float_as_uint(avA.x), aA1 = __float_as_uint(avA.y);
            unsigned aA2 = __float_as_uint(avA.z), aA3 = __float_as_uint(avA.w);
            unsigned aB0 = __float_as_uint(avB.x), aB1 = __float_as_uint(avB.y);
            unsigned aB2 = __float_as_uint(avB.z), aB3 = __float_as_uint(avB.w);
            const float* kbase = Kp + kk * 512 + lr * 8 + lc * 2;
            #pragma unroll
            for (int nt = 0; nt < 8; nt++) {
                float2 bv = *(const float2*)(kbase + nt * 64);
                unsigned b0 = __float_as_uint(bv.x), b1 = __float_as_uint(bv.y);
                mma_tf32(sc[0][nt], aA0, aA1, aA2, aA3, b0, b1);
                mma_tf32(sc[1][nt], aB0, aB1, aB2, aB3, b0, b1);
            }
        }

        // ---- Online softmax maxes (4 row-groups: lr, lr+8, 16+lr, 24+lr) ----
        float r0 = -CUDART_INF_F, r1 = -CUDART_INF_F;
        float r2 = -CUDART_INF_F, r3 = -CUDART_INF_F;
        #pragma unroll
        for (int nt = 0; nt < 8; nt++) {
            r0 = fmaxf(r0, fmaxf(sc[0][nt][0], sc[0][nt][1]));
            r1 = fmaxf(r1, fmaxf(sc[0][nt][2], sc[0][nt][3]));
            r2 = fmaxf(r2, fmaxf(sc[1][nt][0], sc[1][nt][1]));
            r3 = fmaxf(r3, fmaxf(sc[1][nt][2], sc[1][nt][3]));
        }
        r0 = fmaxf(r0, __shfl_xor_sync(0xffffffffu, r0, 1));
        r0 = fmaxf(r0, __shfl_xor_sync(0xffffffffu, r0, 2));
        r1 = fmaxf(r1, __shfl_xor_sync(0xffffffffu, r1, 1));
        r1 = fmaxf(r1, __shfl_xor_sync(0xffffffffu, r1, 2));
        r2 = fmaxf(r2, __shfl_xor_sync(0xffffffffu, r2, 1));
        r2 = fmaxf(r2, __shfl_xor_sync(0xffffffffu, r2, 2));
        r3 = fmaxf(r3, __shfl_xor_sync(0xffffffffu, r3, 1));
        r3 = fmaxf(r3, __shfl_xor_sync(0xffffffffu, r3, 2));
        float mn0 = fmaxf(m[0], r0), mn1 = fmaxf(m[1], r1);
        float mn2 = fmaxf(m[2], r2), mn3 = fmaxf(m[3], r3);
        float c0 = __expf(m[0] - mn0), c1 = __expf(m[1] - mn1);
        float c2 = __expf(m[2] - mn2), c3 = __expf(m[3] - mn3);
        #pragma unroll
        for (int nt = 0; nt < 8; nt++) {
            o[0][nt][0] *= c0; o[0][nt][1] *= c0;
            o[0][nt][2] *= c1; o[0][nt][3] *= c1;
            o[1][nt][0] *= c2; o[1][nt][1] *= c2;
            o[1][nt][2] *= c3; o[1][nt][3] *= c3;
        }

        // ---- PV in two 4-slice batches ----
        float s0 = 0.f, s1 = 0.f, s2 = 0.f, s3 = 0.f;
        #pragma unroll
        for (int ph = 0; ph < 2; ph++) {
            int base_nt = ph * 4;
            if (ph) __syncwarp();     // phase-A reads done before overwrite
            #pragma unroll
            for (int j = 0; j < 4; j++) {
                int nt = base_nt + j;
                float p00 = __expf(sc[0][nt][0] - mn0);
                float p01 = __expf(sc[0][nt][1] - mn0);
                float p02 = __expf(sc[0][nt][2] - mn1);
                float p03 = __expf(sc[0][nt][3] - mn1);
                float p10 = __expf(sc[1][nt][0] - mn2);
                float p11 = __expf(sc[1][nt][1] - mn2);
                float p12 = __expf(sc[1][nt][2] - mn3);
                float p13 = __expf(sc[1][nt][3] - mn3);
                s0 += p00 + p01; s1 += p02 + p03;
                s2 += p10 + p11; s3 += p12 + p13;
                float* Pb0 = PpW + j * 256;          // g=0
                float* Pb1 = PpW + j * 256 + 128;    // g=1
                *(float2*)(Pb0 +      lane * 2) = make_float2(tf32f(p00), tf32f(p02));
                *(float2*)(Pb0 + 64 + lane * 2) = make_float2(tf32f(p01), tf32f(p03));
                *(float2*)(Pb1 +      lane * 2) = make_float2(tf32f(p10), tf32f(p12));
                *(float2*)(Pb1 + 64 + lane * 2) = make_float2(tf32f(p11), tf32f(p13));
            }
            __syncwarp();
            #pragma unroll
            for (int j = 0; j < 4; j++) {
                int kk = base_nt + j;
                int poff = (lc & 1) * 64 + (lr * 4 + (lc >> 1)) * 2;
                const float* pb0 = PpW + j * 256 + poff;
                const float* pb1 = pb0 + 128;
                float2 A01 = *(const float2*)pb0;
                float2 A23 = *(const float2*)(pb0 + 4);
                float2 B01 = *(const float2*)pb1;
                float2 B23 = *(const float2*)(pb1 + 4);
                unsigned aA0 = __float_as_uint(A01.x), aA1 = __float_as_uint(A01.y);
                unsigned aA2 = __float_as_uint(A23.x), aA3 = __float_as_uint(A23.y);
                unsigned aB0 = __float_as_uint(B01.x), aB1 = __float_as_uint(B01.y);
                unsigned aB2 = __float_as_uint(B23.x), aB3 = __float_as_uint(B23.y);
                const float* vbase = Vp + kk * 512 + lr * 8 + lc * 2;
                #pragma unroll
                for (int nt2 = 0; nt2 < 8; nt2++) {
                    float2 bv = *(const float2*)(vbase + nt2 * 64);
                    unsigned b0 = __float_as_uint(bv.x), b1 = __float_as_uint(bv.y);
                    mma_tf32(o[0][nt2], aA0, aA1, aA2, aA3, b0, b1);
                    mma_tf32(o[1][nt2], aB0, aB1, aB2, aB3, b0, b1);
                }
            }
        }
        s0 += __shfl_xor_sync(0xffffffffu, s0, 1);
        s0 += __shfl_xor_sync(0xffffffffu, s0, 2);
        s1 += __shfl_xor_sync(0xffffffffu, s1, 1);
        s1 += __shfl_xor_sync(0xffffffffu, s1, 2);
        s2 += __shfl_xor_sync(0xffffffffu, s2, 1);
        s2 += __shfl_xor_sync(0xffffffffu, s2, 2);
        s3 += __shfl_xor_sync(0xffffffffu, s3, 1);
        s3 += __shfl_xor_sync(0xffffffffu, s3, 2);
        l[0] = l[0] * c0 + s0;
        l[1] = l[1] * c1 + s1;
        l[2] = l[2] * c2 + s2;
        l[3] = l[3] * c3 + s3;
        m[0] = mn0; m[1] = mn1; m[2] = mn2; m[3] = mn3;
    }

    // Epilogue: normalize and scatter to g_o
    float inv0 = 1.f / l[0], inv1 = 1.f / l[1];
    float inv2 = 1.f / l[2], inv3 = 1.f / l[3];
    int r0r = qb * 128 + wid * 32 + lr;
    float* og = g_o + (size_t)b * LL * CC + h * DD;
    #pragma unroll
    for (int nt = 0; nt < 8; nt++) {
        float2 w0 = make_float2(o[0][nt][0] * inv0, o[0][nt][1] * inv0);
        float2 w1 = make_float2(o[0][nt][2] * inv1, o[0][nt][3] * inv1);
        float2 w2 = make_float2(o[1][nt][0] * inv2, o[1][nt][1] * inv2);
        float2 w3 = make_float2(o[1][nt][2] * inv3, o[1][nt][3] * inv3);
        *(float2*)&og[(size_t)(r0r     ) * CC + nt * 8 + 2 * lc] = w0;
        *(float2*)&og[(size_t)(r0r +  8) * CC + nt * 8 + 2 * lc] = w1;
        *(float2*)&og[(size_t)(r0r + 16) * CC + nt * 8 + 2 * lc] = w2;
        *(float2*)&og[(size_t)(r0r + 24) * CC + nt * 8 + 2 * lc] = w3;
    }
}

// ---------------------------------------------------------------------------
extern "C" void kernel_launch(void* const* d_in, const int* in_sizes, int n_in,
                              void* d_out, int out_size) {
    const float* x     = (const float*)d_in[0];
    const float* Wqkv  = (const float*)d_in[1];
    const float* bqkv  = (const float*)d_in[2];
    const float* Wproj = (const float*)d_in[3];
    const float* bproj = (const float*)d_in[4];
    float* out = (float*)d_out;

    cudaFuncSetAttribute(attn_tf32, cudaFuncAttributeMaxDynamicSharedMemorySize,
                         ATT_SMEM_BYTES);
    cudaFuncSetAttribute(gemm_tf32<NQKV, true>,
                         cudaFuncAttributeMaxDynamicSharedMemorySize, GEMM_SMEM_BYTES);
    cudaFuncSetAttribute(gemm_tf32<CC, false>,
                         cudaFuncAttributeMaxDynamicSharedMemorySize, GEMM_SMEM_BYTES);

    gemm_tf32<NQKV, true><<<dim3(NQKV / 64, MM / 128), 256, GEMM_SMEM_BYTES>>>(
        x, Wqkv, bqkv, nullptr);
    meansim_kernel<<<dim3(NQ + NK, BB * HH), 256>>>();
    mask_kernel<<<BB * HH, 256>>>();
    attn_tf32<<<dim3(NQ, BB * HH), 128, ATT_SMEM_BYTES>>>();
    gemm_tf32<CC, false><<<dim3(CC / 64, MM / 128), 256, GEMM_SMEM_BYTES>>>(
        nullptr, Wproj, bproj, out);
}

// round 14
// speedup vs baseline: 1.7685x; 1.0892x over previous
#include <cuda_runtime.h>
#include <cuda_bf16.h>
#include <math_constants.h>

// Problem constants
#define BB   2
#define LL   2048
#define CC   512
#define HH   8
#define DD   64
#define MM   (BB*LL)          // 4096 rows
#define NQKV (3*CC)           // 1536
#define NQ   16               // L/128 (mask Q-block granularity)
#define NK   32               // L/64
#define SCALE 0.125f          // D^-0.5
#define SIMTH 0.6f
#define CDFTH 0.98f

// Scratch (allocation-free rule -> device globals)
__device__ float g_q[BB*HH*LL*DD];        // raw [B,H,L,D] (meansim)
__device__ float g_k[BB*HH*LL*DD];        // raw [B,H,L,D] (meansim)
__device__ float g_qp[BB*HH*NQ*8192];     // Q A-fragments, tf32(q*SCALE)  (128x64)
__device__ float g_kp[BB*HH*NK*4096];     // K B-frag pairs, tf32          (64x64)
__device__ float g_vp[BB*HH*NK*4096];     // V B-frag pairs, tf32          (64x64)
__device__ float g_o[BB*LL*CC];           // [B,L,C]
__device__ int   g_mask[BB*HH*NQ*NK];     // 1 = keep block
__device__ float g_qm[BB*HH][NQ][DD];
__device__ float g_km[BB*HH][NK][DD];
__device__ float g_qsim[BB*HH][NQ];
__device__ float g_ksim[BB*HH][NK];

__device__ __forceinline__ unsigned f2tf32(float x) {
    unsigned r;
    asm("cvt.rna.tf32.f32 %0, %1;" : "=r"(r) : "f"(x));
    return r;
}
__device__ __forceinline__ float tf32f(float x) {
    return __uint_as_float(f2tf32(x));
}

__device__ __forceinline__ void mma_tf32(float c[4],
                                         unsigned a0, unsigned a1, unsigned a2, unsigned a3,
                                         unsigned b0, unsigned b1) {
    asm volatile(
        "mma.sync.aligned.m16n8k8.row.col.f32.tf32.tf32.f32 "
        "{%0,%1,%2,%3}, {%4,%5,%6,%7}, {%8,%9}, {%0,%1,%2,%3};"
        : "+f"(c[0]), "+f"(c[1]), "+f"(c[2]), "+f"(c[3])
        : "r"(a0), "r"(a1), "r"(a2), "r"(a3), "r"(b0), "r"(b1));
}

__device__ __forceinline__ void cp16(unsigned smem_dst, const void* gsrc) {
    asm volatile("cp.async.ca.shared.global [%0], [%1], 16;"
                 :: "r"(smem_dst), "l"(gsrc));
}

__device__ __forceinline__ void atomicMinFloat(float* addr, float val) {
    int* ia = (int*)addr;
    int old = *ia;
    while (__int_as_float(old) > val) {
        int assumed = old;
        old = atomicCAS(ia, assumed, __float_as_int(val));
        if (old == assumed) break;
    }
}

// ---------------------------------------------------------------------------
// tf32 tensor-core GEMM: C[M,N] = A[M,K=512] @ B[K,N] + bias
// 128x128 tile, 256 threads = 8 warps (4M x 2N), warp tile 32x64,
// cp.async double-buffered.  SCATTER=true: writes raw q/k + packed qp/kp/vp.
// ---------------------------------------------------------------------------
#define GA_ST 36
#define GB_ST 136
#define GA_FL (128*GA_ST)          // 4608
#define GB_FL (32*GB_ST)           // 4352
#define GEMM_SMEM_FLOATS (2*GA_FL + 2*GB_FL)
#define GEMM_SMEM_BYTES  (GEMM_SMEM_FLOATS*4)   // 71680

extern __shared__ float sm_dyn[];

template<int N, bool SCATTER>
__global__ void __launch_bounds__(256) gemm_tf32(const float* __restrict__ A,
                                                 const float* __restrict__ Bw,
                                                 const float* __restrict__ bias,
                                                 float* __restrict__ out) {
    const int K = CC;
    const float* Ap = SCATTER ? A : (const float*)g_o;
    int m0 = blockIdx.y * 128, n0 = blockIdx.x * 128;
    float* Asm = sm_dyn;
    float* Bsm = sm_dyn + 2 * GA_FL;
    unsigned sbase = (unsigned)__cvta_generic_to_shared(sm_dyn);
    int tid = threadIdx.x;
    int wid = tid >> 5, lane = tid & 31;
    int lr = lane >> 2, lc = lane & 3;
    int warp_m = wid & 3, warp_n = wid >> 2;

    float c[2][8][4] = {};

    auto stage = [&](int buf, int k0) {
        unsigned a_s = sbase + (unsigned)(buf * GA_FL) * 4u;
        unsigned b_s = sbase + (unsigned)(2 * GA_FL + buf * GB_FL) * 4u;
        #pragma unroll
        for (int i = 0; i < 4; i++) {
            int f4 = tid + i * 256;              // 1024 f4 of A (128x32)
            int r = f4 >> 3, cg = f4 & 7;
            cp16(a_s + (unsigned)(r * GA_ST + cg * 4) * 4u,
                 &Ap[(size_t)(m0 + r) * K + k0 + cg * 4]);
        }
        #pragma unroll
        for (int i = 0; i < 4; i++) {
            int f4 = tid + i * 256;              // 1024 f4 of B (32x128)
            int r = f4 >> 5, cg = f4 & 31;
            cp16(b_s + (unsigned)(r * GB_ST + cg * 4) * 4u,
                 &Bw[(size_t)(k0 + r) * N + n0 + cg * 4]);
        }
        asm volatile("cp.async.commit_group;");
    };

    stage(0, 0);
    const int NCHUNK = K / 32;
    for (int ch = 0; ch < NCHUNK; ch++) {
        int buf = ch & 1;
        if (ch < NCHUNK - 1) {
            stage(buf ^ 1, (ch + 1) * 32);
            asm volatile("cp.async.wait_group 1;");
        } else {
            asm volatile("cp.async.wait_group 0;");
        }
        __syncthreads();

        const float* Aw = Asm + buf * GA_FL + (warp_m * 32) * GA_ST;
        const float* Bb = Bsm + buf * GB_FL;
        #pragma unroll
        for (int kk = 0; kk < 4; kk++) {
            int kf = kk * 8;
            unsigned a[2][4];
            #pragma unroll
            for (int mt = 0; mt < 2; mt++) {
                a[mt][0] = f2tf32(Aw[(mt * 16 + lr    ) * GA_ST + kf + lc    ]);
                a[mt][1] = f2tf32(Aw[(mt * 16 + lr + 8) * GA_ST + kf + lc    ]);
                a[mt][2] = f2tf32(Aw[(mt * 16 + lr    ) * GA_ST + kf + lc + 4]);
                a[mt][3] = f2tf32(Aw[(mt * 16 + lr + 8) * GA_ST + kf + lc + 4]);
            }
            unsigned bf[8][2];
            #pragma unroll
            for (int nt = 0; nt < 8; nt++) {
                int nn = warp_n * 64 + nt * 8 + lr;
                bf[nt][0] = f2tf32(Bb[(kf + lc    ) * GB_ST + nn]);
                bf[nt][1] = f2tf32(Bb[(kf + lc + 4) * GB_ST + nn]);
            }
            #pragma unroll
            for (int mt = 0; mt < 2; mt++)
                #pragma unroll
                for (int nt = 0; nt < 8; nt++)
                    mma_tf32(c[mt][nt], a[mt][0], a[mt][1], a[mt][2], a[mt][3],
                             bf[nt][0], bf[nt][1]);
        }
        __syncthreads();
    }

    // Epilogue
    int t = n0 >> 9;   // uniform per CTA when SCATTER (128-col tile never straddles 512)
    #pragma unroll
    for (int mt = 0; mt < 2; mt++) {
        #pragma unroll
        for (int half = 0; half < 2; half++) {
            int row = m0 + warp_m * 32 + mt * 16 + lr + half * 8;
            #pragma unroll
            for (int nt = 0; nt < 8; nt++) {
                int col = n0 + warp_n * 64 + nt * 8 + 2 * lc;
                float v0 = c[mt][nt][half * 2 + 0] + bias[col];
                float v1 = c[mt][nt][half * 2 + 1] + bias[col + 1];
                if (SCATTER) {
                    int b = row >> 11, l = row & 2047;
                    int h = (col & 511) >> 6;
                    int d = col & 63, d1 = d + 1;
                    int bh = b * HH + h;
                    if (t == 0) {
                        *(float2*)&g_q[((size_t)bh * LL + l) * DD + d] =
                            make_float2(v0, v1);
                        int qt = l >> 7, r = l & 127;
                        int w = r >> 4, lr2 = r & 7, hf = (r >> 3) & 1;
                        float* qp = g_qp + ((size_t)(bh * NQ + qt)) * 8192 + w * 1024;
                        qp[(d  >> 3) * 128 + (lr2 * 4 + (d  & 3)) * 4 + hf + 2 * ((d  >> 2) & 1)]
                            = tf32f(v0 * SCALE);
                        qp[(d1 >> 3) * 128 + (lr2 * 4 + (d1 & 3)) * 4 + hf + 2 * ((d1 >> 2) & 1)]
                            = tf32f(v1 * SCALE);
                    } else if (t == 1) {
                        *(float2*)&g_k[((size_t)bh * LL + l) * DD + d] =
                            make_float2(v0, v1);
                        int kb = l >> 6, n = l & 63;
                        float* kp = g_kp + ((size_t)(bh * NK + kb)) * 4096 + n * 8;
                        kp[(d  >> 3) * 512 + (d  & 3) * 2 + ((d  >> 2) & 1)] = tf32f(v0);
                        kp[(d1 >> 3) * 512 + (d1 & 3) * 2 + ((d1 >> 2) & 1)] = tf32f(v1);
                    } else {
                        int kb = l >> 6, k64 = l & 63;
                        float* vp = g_vp + ((size_t)(bh * NK + kb)) * 4096
                                  + (k64 >> 3) * 512 + (k64 & 3) * 2 + ((k64 >> 2) & 1);
                        vp[d  * 8] = tf32f(v0);
                        vp[d1 * 8] = tf32f(v1);
                    }
                } else {
                    *(float2*)&out[(size_t)row * N + col] = make_float2(v0, v1);
                }
            }
        }
    }
}

// ---------------------------------------------------------------------------
// Kernel 2a: per-block mean + min-cosine.
// ---------------------------------------------------------------------------
__global__ void __launch_bounds__(256) meansim_kernel() {
    int bh = blockIdx.y;
    int j  = blockIdx.x;
    bool isQ = j < NQ;
    int blk  = isQ ? j : j - NQ;
    int rows = isQ ? 128 : 64;
    const float* base = (isQ ? g_q : g_k) + (size_t)bh * LL * DD + (size_t)blk * rows * DD;
    __shared__ float psum[256];
    __shared__ float mean[64];
    __shared__ float nrm;
    __shared__ float simv;
    int tid = threadIdx.x;
    if (tid == 0) simv = 1e30f;

    {
        int d = tid & 63, rg = tid >> 6;
        float acc = 0.f;
        for (int r = rg; r < rows; r += 4) acc += base[r * DD + d];
        psum[tid] = acc;
    }
    __syncthreads();
    if (tid < 64) {
        float m = (psum[tid] + psum[tid + 64] + psum[tid + 128] + psum[tid + 192])
                  * (1.f / rows);
        mean[tid] = m;
        float* gm = isQ ? &g_qm[bh][blk][0] : &g_km[bh][blk][0];
        gm[tid] = m;
    }
    __syncthreads();
    if (tid < 32) {
        float s = mean[tid] * mean[tid] + mean[tid + 32] * mean[tid + 32];
        #pragma unroll
        for (int o = 16; o >= 1; o >>= 1) s += __shfl_xor_sync(0xffffffffu, s, o);
        if (tid == 0) nrm = sqrtf(s);
    }
    __syncthreads();
    float mnorm = nrm;

    float cosv;
    if (isQ) {
        int row = tid >> 1, half = tid & 1;
        const float* p  = base + row * DD + half * 32;
        const float* mp = mean + half * 32;
        float dot = 0.f, nn = 0.f;
        #pragma unroll
        for (int d = 0; d < 32; d++) { float v = p[d]; dot += v * mp[d]; nn += v * v; }
        dot += __shfl_xor_sync(0xffffffffu, dot, 1);
        nn  += __shfl_xor_sync(0xffffffffu, nn,  1);
        cosv = dot / ((sqrtf(nn) + 1e-6f) * (mnorm + 1e-6f));
    } else {
        int row = tid >> 2, qd = tid & 3;
        const float* p  = base + row * DD + qd * 16;
        const float* mp = mean + qd * 16;
        float dot = 0.f, nn = 0.f;
        #pragma unroll
        for (int d = 0; d < 16; d++) { float v = p[d]; dot += v * mp[d]; nn += v * v; }
        dot += __shfl_xor_sync(0xffffffffu, dot, 1);
        dot += __shfl_xor_sync(0xffffffffu, dot, 2);
        nn  += __shfl_xor_sync(0xffffffffu, nn,  1);
        nn  += __shfl_xor_sync(0xffffffffu, nn,  2);
        cosv = dot / ((sqrtf(nn) + 1e-6f) * (mnorm + 1e-6f));
    }
    #pragma unroll
    for (int o = 16; o >= 1; o >>= 1)
        cosv = fminf(cosv, __shfl_xor_sync(0xffffffffu, cosv, o));
    if ((tid & 31) == 0) atomicMinFloat(&simv, cosv);
    __syncthreads();
    if (tid == 0) {
        if (isQ) g_qsim[bh][blk] = simv; else g_ksim[bh][blk] = simv;
    }
}

// ---------------------------------------------------------------------------
// Kernel 2b: pooled softmax + CDF keep -> block mask.
// ---------------------------------------------------------------------------
__global__ void __launch_bounds__(256) mask_kernel() {
    int bh = blockIdx.x;
    __shared__ float pooled[NQ][NK];
    __shared__ float qs[NQ], kss[NK];
    int tid = threadIdx.x;
    if (tid < NQ) qs[tid]  = g_qsim[bh][tid];
    if (tid < NK) kss[tid] = g_ksim[bh][tid];
    for (int e = tid; e < NQ * NK; e += 256) {
        int qi = e >> 5, ki = e & 31;
        const float* a = g_qm[bh][qi];
        const float* b = g_km[bh][ki];
        float dot = 0.f;
        #pragma unroll
        for (int d = 0; d < DD; d++) dot += a[d] * b[d];
        pooled[qi][ki] = dot * SCALE;
    }
    __syncthreads();
    if (tid < NQ) {
        float vals[NK]; int idx[NK];
        float mx = -CUDART_INF_F;
        for (int i = 0; i < NK; i++) mx = fmaxf(mx, pooled[tid][i]);
        float sum = 0.f;
        for (int i = 0; i < NK; i++) { vals[i] = expf(pooled[tid][i] - mx); sum += vals[i]; }
        float inv = 1.f / sum;
        for (int i = 0; i < NK; i++) { vals[i] *= inv; idx[i] = i; }
        for (int i = 1; i < NK; i++) {
            float kv = vals[i]; int ki = idx[i];
            int j = i - 1;
            while (j >= 0 && vals[j] < kv) { vals[j+1] = vals[j]; idx[j+1] = idx[j]; j--; }
            vals[j+1] = kv; idx[j+1] = ki;
        }
        unsigned keep = 0u;
        float csum = 0.f;
        for (int i = 0; i < NK; i++) {
            if (csum < CDFTH) keep |= (1u << idx[i]);
            csum += vals[i];
        }
        bool qself = qs[tid] > SIMTH;
        int* mrow = g_mask + (bh * NQ + tid) * NK;
        for (int ki = 0; ki < NK; ki++) {
            bool kself = kss[ki] > SIMTH;
            mrow[ki] = (((keep >> ki) & 1u) || !qself || !kself) ? 1 : 0;
        }
    }
}

// ---------------------------------------------------------------------------
// Kernel 3: block-sparse flash attention, tf32 mma, fragment-packed operands.
// 4 warps x 32 q-rows; Q A-fragments held in REGISTERS (loaded once via LDG
// from g_qp) -> no Qp smem, no per-kblock Q LDS.  K/V double-buffered
// cp.async prefetch; PV in two 4-slice batches.
// grid = (16 q-tiles of 128 rows, 16 bh), 128 threads = 4 warps.
// smem: K0/K1[4096 ea] | V0/V1[4096 ea] | Pp[4 w][1024] = 20480 fl = 80 KB
//   -> 2 CTAs/SM (160 KB); regs ~220 (cap 256 at 2x128 thr).
// ---------------------------------------------------------------------------
#define ATT_KV_FL 4096
#define ATT_SMEM_FLOATS (4*ATT_KV_FL + 4*1024)   // 20480
#define ATT_SMEM_BYTES  (ATT_SMEM_FLOATS * 4)    // 81920

__global__ void __launch_bounds__(128, 2) attn_tf32() {
    const int qb = blockIdx.x;
    const int bh = blockIdx.y;
    const int b = bh >> 3, h = bh & 7;
    const int tid  = threadIdx.x;
    const int wid  = tid >> 5;          // 0..3, warp owns rows wid*32..wid*32+31
    const int lane = tid & 31;
    const int lr = lane >> 2;
    const int lc = lane & 3;

    float* Kbuf = sm_dyn;                                   // [2][4096]
    float* Vbuf = sm_dyn + 2 * ATT_KV_FL;                   // [2][4096]
    float* PpW  = Vbuf + 2 * ATT_KV_FL + wid * 1024;        // [4 slice][2 g][2 c2][32 L][2]
    unsigned sbase  = (unsigned)__cvta_generic_to_shared(sm_dyn);
    unsigned kbuf_u = sbase;
    unsigned vbuf_u = sbase + 2u * ATT_KV_FL * 4u;

    __shared__ int s_list[NK];
    __shared__ int s_nk;

    // Q A-fragments -> registers (loop-invariant; coalesced LDG.128)
    unsigned qreg[2][8][4];
    {
        const float* qg = g_qp + ((size_t)(bh * NQ + qb)) * 8192 + (2 * wid) * 1024;
        #pragma unroll
        for (int g = 0; g < 2; g++)
            #pragma unroll
            for (int kk = 0; kk < 8; kk++) {
                float4 v = *(const float4*)(qg + g * 1024 + kk * 128 + lane * 4);
                qreg[g][kk][0] = __float_as_uint(v.x);
                qreg[g][kk][1] = __float_as_uint(v.y);
                qreg[g][kk][2] = __float_as_uint(v.z);
                qreg[g][kk][3] = __float_as_uint(v.w);
            }
    }

    // Kept-block list
    const int* mrow = g_mask + (bh * NQ + qb) * NK;
    if (tid == 0) {
        int c = 0;
        for (int i = 0; i < NK; i++) if (mrow[i]) s_list[c++] = i;
        s_nk = c;
    }
    __syncthreads();
    const int nkeep = s_nk;

    const float* kgp = g_kp + (size_t)bh * NK * 4096;
    const float* vgp = g_vp + (size_t)bh * NK * 4096;

    auto stage_kv = [&](int buf, int kb) {
        const float* ks = kgp + (size_t)kb * 4096;
        const float* vs = vgp + (size_t)kb * 4096;
        unsigned ko = kbuf_u + (unsigned)(buf * ATT_KV_FL) * 4u;
        unsigned vo = vbuf_u + (unsigned)(buf * ATT_KV_FL) * 4u;
        #pragma unroll
        for (int i = 0; i < 8; i++) {
            unsigned off = (unsigned)(tid + i * 128) * 16u;
            cp16(ko + off, ks + (tid + i * 128) * 4);
            cp16(vo + off, vs + (tid + i * 128) * 4);
        }
        asm volatile("cp.async.commit_group;");
    };

    stage_kv(0, s_list[0]);

    float o[2][8][4];
    #pragma unroll
    for (int g = 0; g < 2; g++)
        #pragma unroll
        for (int nt = 0; nt < 8; nt++)
            #pragma unroll
            for (int j = 0; j < 4; j++) o[g][nt][j] = 0.f;
    float m[4] = {-CUDART_INF_F, -CUDART_INF_F, -CUDART_INF_F, -CUDART_INF_F};
    float l[4] = {0.f, 0.f, 0.f, 0.f};

    for (int i = 0; i < nkeep; i++) {
        int buf = i & 1;
        asm volatile("cp.async.wait_group 0;");
        __syncthreads();               // staged data visible; prev iter reads done
        if (i + 1 < nkeep) stage_kv(buf ^ 1, s_list[i + 1]);

        const float* Kp = Kbuf + buf * ATT_KV_FL;
        const float* Vp = Vbuf + buf * ATT_KV_FL;

        // ---- S = Q K^T : 32 rows x 64 kpos per warp ----
        float sc[2][8][4];
        #pragma unroll
        for (int g = 0; g < 2; g++)
            #pragma unroll
            for (int nt = 0; nt < 8; nt++)
                #pragma unroll
                for (int j = 0; j < 4; j++) sc[g][nt][j] = 0.f;

        #pragma unroll
        for (int kk = 0; kk < 8; kk++) {
            const float* kbase = Kp + kk * 512 + lr * 8 + lc * 2;
            #pragma unroll
            for (int nt = 0; nt < 8; nt++) {
                float2 bv = *(const float2*)(kbase + nt * 64);
                unsigned b0 = __float_as_uint(bv.x), b1 = __float_as_uint(bv.y);
                mma_tf32(sc[0][nt], qreg[0][kk][0], qreg[0][kk][1],
                         qreg[0][kk][2], qreg[0][kk][3], b0, b1);
                mma_tf32(sc[1][nt], qreg[1][kk][0], qreg[1][kk][1],
                         qreg[1][kk][2], qreg[1][kk][3], b0, b1);
            }
        }

        // ---- Online softmax maxes (4 row-groups: lr, lr+8, 16+lr, 24+lr) ----
        float r0 = -CUDART_INF_F, r1 = -CUDART_INF_F;
        float r2 = -CUDART_INF_F, r3 = -CUDART_INF_F;
        #pragma unroll
        for (int nt = 0; nt < 8; nt++) {
            r0 = fmaxf(r0, fmaxf(sc[0][nt][0], sc[0][nt][1]));
            r1 = fmaxf(r1, fmaxf(sc[0][nt][2], sc[0][nt][3]));
            r2 = fmaxf(r2, fmaxf(sc[1][nt][0], sc[1][nt][1]));
            r3 = fmaxf(r3, fmaxf(sc[1][nt][2], sc[1][nt][3]));
        }
        r0 = fmaxf(r0, __shfl_xor_sync(0xffffffffu, r0, 1));
        r0 = fmaxf(r0, __shfl_xor_sync(0xffffffffu, r0, 2));
        r1 = fmaxf(r1, __shfl_xor_sync(0xffffffffu, r1, 1));
        r1 = fmaxf(r1, __shfl_xor_sync(0xffffffffu, r1, 2));
        r2 = fmaxf(r2, __shfl_xor_sync(0xffffffffu, r2, 1));
        r2 = fmaxf(r2, __shfl_xor_sync(0xffffffffu, r2, 2));
        r3 = fmaxf(r3, __shfl_xor_sync(0xffffffffu, r3, 1));
        r3 = fmaxf(r3, __shfl_xor_sync(0xffffffffu, r3, 2));
        float mn0 = fmaxf(m[0], r0), mn1 = fmaxf(m[1], r1);
        float mn2 = fmaxf(m[2], r2), mn3 = fmaxf(m[3], r3);
        float c0 = __expf(m[0] - mn0), c1 = __expf(m[1] - mn1);
        float c2 = __expf(m[2] - mn2), c3 = __expf(m[3] - mn3);
        #pragma unroll
        for (int nt = 0; nt < 8; nt++) {
            o[0][nt][0] *= c0; o[0][nt][1] *= c0;
            o[0][nt][2] *= c1; o[0][nt][3] *= c1;
            o[1][nt][0] *= c2; o[1][nt][1] *= c2;
            o[1][nt][2] *= c3; o[1][nt][3] *= c3;
        }

        // ---- PV in two 4-slice batches ----
        float s0 = 0.f, s1 = 0.f, s2 = 0.f, s3 = 0.f;
        #pragma unroll
        for (int ph = 0; ph < 2; ph++) {
            int base_nt = ph * 4;
            if (ph) __syncwarp();     // phase-A reads done before overwrite
            #pragma unroll
            for (int j = 0; j < 4; j++) {
                int nt = base_nt + j;
                float p00 = __expf(sc[0][nt][0] - mn0);
                float p01 = __expf(sc[0][nt][1] - mn0);
                float p02 = __expf(sc[0][nt][2] - mn1);
                float p03 = __expf(sc[0][nt][3] - mn1);
                float p10 = __expf(sc[1][nt][0] - mn2);
                float p11 = __expf(sc[1][nt][1] - mn2);
                float p12 = __expf(sc[1][nt][2] - mn3);
                float p13 = __expf(sc[1][nt][3] - mn3);
                s0 += p00 + p01; s1 += p02 + p03;
                s2 += p10 + p11; s3 += p12 + p13;
                float* Pb0 = PpW + j * 256;          // g=0
                float* Pb1 = PpW + j * 256 + 128;    // g=1
                *(float2*)(Pb0 +      lane * 2) = make_float2(tf32f(p00), tf32f(p02));
                *(float2*)(Pb0 + 64 + lane * 2) = make_float2(tf32f(p01), tf32f(p03));
                *(float2*)(Pb1 +      lane * 2) = make_float2(tf32f(p10), tf32f(p12));
                *(float2*)(Pb1 + 64 + lane * 2) = make_float2(tf32f(p11), tf32f(p13));
            }
            __syncwarp();
            #pragma unroll
            for (int j = 0; j < 4; j++) {
                int kk = base_nt + j;
                int poff = (lc & 1) * 64 + (lr * 4 + (lc >> 1)) * 2;
                const float* pb0 = PpW + j * 256 + poff;
                const float* pb1 = pb0 + 128;
                float2 A01 = *(const float2*)pb0;
                float2 A23 = *(const float2*)(pb0 + 4);
                float2 B01 = *(const float2*)pb1;
                float2 B23 = *(const float2*)(pb1 + 4);
                unsigned aA0 = __float_as_uint(A01.x), aA1 = __float_as_uint(A01.y);
                unsigned aA2 = __float_as_uint(A23.x), aA3 = __float_as_uint(A23.y);
                unsigned aB0 = __float_as_uint(B01.x), aB1 = __float_as_uint(B01.y);
                unsigned aB2 = __float_as_uint(B23.x), aB3 = __float_as_uint(B23.y);
                const float* vbase = Vp + kk * 512 + lr * 8 + lc * 2;
                #pragma unroll
                for (int nt2 = 0; nt2 < 8; nt2++) {
                    float2 bv = *(const float2*)(vbase + nt2 * 64);
                    unsigned b0 = __float_as_uint(bv.x), b1 = __float_as_uint(bv.y);
                    mma_tf32(o[0][nt2], aA0, aA1, aA2, aA3, b0, b1);
                    mma_tf32(o[1][nt2], aB0, aB1, aB2, aB3, b0, b1);
                }
            }
        }
        s0 += __shfl_xor_sync(0xffffffffu, s0, 1);
        s0 += __shfl_xor_sync(0xffffffffu, s0, 2);
        s1 += __shfl_xor_sync(0xffffffffu, s1, 1);
        s1 += __shfl_xor_sync(0xffffffffu, s1, 2);
        s2 += __shfl_xor_sync(0xffffffffu, s2, 1);
        s2 += __shfl_xor_sync(0xffffffffu, s2, 2);
        s3 += __shfl_xor_sync(0xffffffffu, s3, 1);
        s3 += __shfl_xor_sync(0xffffffffu, s3, 2);
        l[0] = l[0] * c0 + s0;
        l[1] = l[1] * c1 + s1;
        l[2] = l[2] * c2 + s2;
        l[3] = l[3] * c3 + s3;
        m[0] = mn0; m[1] = mn1; m[2] = mn2; m[3] = mn3;
    }

    // Epilogue: normalize and scatter to g_o
    float inv0 = 1.f / l[0], inv1 = 1.f / l[1];
    float inv2 = 1.f / l[2], inv3 = 1.f / l[3];
    int r0r = qb * 128 + wid * 32 + lr;
    float* og = g_o + (size_t)b * LL * CC + h * DD;
    #pragma unroll
    for (int nt = 0; nt < 8; nt++) {
        float2 w0 = make_float2(o[0][nt][0] * inv0, o[0][nt][1] * inv0);
        float2 w1 = make_float2(o[0][nt][2] * inv1, o[0][nt][3] * inv1);
        float2 w2 = make_float2(o[1][nt][0] * inv2, o[1][nt][1] * inv2);
        float2 w3 = make_float2(o[1][nt][2] * inv3, o[1][nt][3] * inv3);
        *(float2*)&og[(size_t)(r0r     ) * CC + nt * 8 + 2 * lc] = w0;
        *(float2*)&og[(size_t)(r0r +  8) * CC + nt * 8 + 2 * lc] = w1;
        *(float2*)&og[(size_t)(r0r + 16) * CC + nt * 8 + 2 * lc] = w2;
        *(float2*)&og[(size_t)(r0r + 24) * CC + nt * 8 + 2 * lc] = w3;
    }
}

// ---------------------------------------------------------------------------
extern "C" void kernel_launch(void* const* d_in, const int* in_sizes, int n_in,
                              void* d_out, int out_size) {
    const float* x     = (const float*)d_in[0];
    const float* Wqkv  = (const float*)d_in[1];
    const float* bqkv  = (const float*)d_in[2];
    const float* Wproj = (const float*)d_in[3];
    const float* bproj = (const float*)d_in[4];
    float* out = (float*)d_out;

    cudaFuncSetAttribute(attn_tf32, cudaFuncAttributeMaxDynamicSharedMemorySize,
                         ATT_SMEM_BYTES);
    cudaFuncSetAttribute(gemm_tf32<NQKV, true>,
                         cudaFuncAttributeMaxDynamicSharedMemorySize, GEMM_SMEM_BYTES);
    cudaFuncSetAttribute(gemm_tf32<CC, false>,
                         cudaFuncAttributeMaxDynamicSharedMemorySize, GEMM_SMEM_BYTES);

    gemm_tf32<NQKV, true><<<dim3(NQKV / 128, MM / 128), 256, GEMM_SMEM_BYTES>>>(
        x, Wqkv, bqkv, nullptr);
    meansim_kernel<<<dim3(NQ + NK, BB * HH), 256>>>();
    mask_kernel<<<BB * HH, 256>>>();
    attn_tf32<<<dim3(NQ, BB * HH), 128, ATT_SMEM_BYTES>>>();
    gemm_tf32<CC, false><<<dim3(CC / 128, MM / 128), 256, GEMM_SMEM_BYTES>>>(
        nullptr, Wproj, bproj, out);
}